// round 6
// baseline (speedup 1.0000x reference)
#include <cuda_runtime.h>
#include <math.h>

// ---------------- problem constants ----------------
#define Bz   64
#define Tt   800
#define Hh   512
#define Kk   10
#define SENT 60
#define G4   2048            // 4*H
#define BT   (Bz*Tt)         // 51200
#define MDNO 121             // 1 + 6*M
#define NBLK 128             // persistent grid (must be <= 148 for co-residency)
#define XP   68              // xsm row pitch (floats): 68 mod 32 == 4 -> conflict-free LDS.128

// ---------------- persistent device scratch (no allocations) ----------------
__device__ float d_hid1[BT*Hh];
__device__ float d_hid2[BT*Hh];
__device__ float d_win [BT*SENT];
__device__ float d_c1  [Bz*Hh];
__device__ float d_c2  [Bz*Hh];
__device__ float d_kbuf[Bz*Kk];
__device__ float d_wbuf[Bz*SENT];

// per-block packed weights: [block][k][16 rows], rows = gate*4+unit
__device__ float d_P1 [NBLK*576*16];    // LSTM1: k 0..63 input(strk3+win60+pad), 64..575 recurrent
__device__ float d_P2 [NBLK*1088*16];   // LSTM2: 0..511 hid1, 512..514 strk, 515..574 win, 575 pad, 576..1087 rec
__device__ float d_b1p[G4];
__device__ float d_b2p[G4];
__device__ float d_Weff[MDNO*1024];     // Wmdn folded (hid3 == hid2)

// grid barrier state
__device__ unsigned          d_bar_count;
__device__ volatile unsigned d_bar_sense;

__device__ __forceinline__ float sigf(float x) { return 1.f/(1.f+expf(-x)); }

// ---------------- prep kernels (one-time) ----------------
__global__ void prep_pack1(const float* __restrict__ Wih1, const float* __restrict__ Whh1) {
    int idx = blockIdx.x*blockDim.x + threadIdx.x;
    if (idx >= NBLK*576*16) return;
    int bb = idx / 9216, rem = idx % 9216;
    int k = rem >> 4, rr = rem & 15;
    int gate = rr >> 2, uu = rr & 3;
    int grow = gate*512 + bb*4 + uu;
    float v;
    if (k < 64) v = (k < 63) ? Wih1[grow*63 + k] : 0.f;   // [strk(3)|win(60)|pad]
    else        v = Whh1[grow*512 + (k-64)];
    d_P1[idx] = v;
}

__global__ void prep_pack2(const float* __restrict__ Wih2, const float* __restrict__ Whh2) {
    int idx = blockIdx.x*blockDim.x + threadIdx.x;
    if (idx >= NBLK*1088*16) return;
    int bb = idx / 17408, rem = idx % 17408;
    int k = rem >> 4, rr = rem & 15;
    int gate = rr >> 2, uu = rr & 3;
    int grow = gate*512 + bb*4 + uu;
    float v;
    if      (k < 512) v = Wih2[grow*575 + 3 + k];          // hid1 cols
    else if (k < 515) v = Wih2[grow*575 + (k-512)];        // strk cols 0..2
    else if (k < 575) v = Wih2[grow*575 + k];              // win cols 515..574
    else if (k == 575) v = 0.f;                            // pad
    else              v = Whh2[grow*512 + (k-576)];        // recurrent
    d_P2[idx] = v;
}

__global__ void prep_bias(const float* __restrict__ bih1, const float* __restrict__ bhh1,
                          const float* __restrict__ bih2, const float* __restrict__ bhh2) {
    int idx = blockIdx.x*blockDim.x + threadIdx.x;
    if (idx >= G4) return;
    int bb = idx >> 4, rr = idx & 15;
    int gate = rr >> 2, uu = rr & 3;
    int grow = gate*512 + bb*4 + uu;
    d_b1p[idx] = bih1[grow] + bhh1[grow];
    d_b2p[idx] = bih2[grow] + bhh2[grow];
}

__global__ void prep_weff(const float* __restrict__ Wmdn) {
    int idx = blockIdx.x*blockDim.x + threadIdx.x;
    if (idx >= MDNO*1024) return;
    int o = idx >> 10, k = idx & 1023;
    float v = Wmdn[o*1536 + k];
    if (k >= 512) v += Wmdn[o*1536 + k + 512];
    d_Weff[idx] = v;
}

__global__ void init_state(const float* __restrict__ w_prev) {
    int idx = blockIdx.x*blockDim.x + threadIdx.x;
    if (idx < Bz*Hh) { d_c1[idx] = 0.f; d_c2[idx] = 0.f; }
    if (idx < Bz*Kk)   d_kbuf[idx] = 0.f;
    if (idx < Bz*SENT) d_wbuf[idx] = w_prev[idx];
    if (idx == 0) { d_bar_count = 0u; d_bar_sense = 0u; }
}

// ---------------- inner 64-k MAC tile ----------------
// xr: this thread's batch row in xsm; wbase: wsm + rq*4 (16-row-major [k][16])
__device__ __forceinline__ void tile_mac(const float* xr, const float* wbase,
                                         float& a0, float& a1, float& a2, float& a3)
{
    #pragma unroll
    for (int k = 0; k < 64; k += 4) {
        float4 xv = *(const float4*)(xr + k);
        float4 w0 = *(const float4*)(wbase + (k+0)*16);
        a0 += w0.x*xv.x; a1 += w0.y*xv.x; a2 += w0.z*xv.x; a3 += w0.w*xv.x;
        float4 w1 = *(const float4*)(wbase + (k+1)*16);
        a0 += w1.x*xv.y; a1 += w1.y*xv.y; a2 += w1.z*xv.y; a3 += w1.w*xv.y;
        float4 w2 = *(const float4*)(wbase + (k+2)*16);
        a0 += w2.x*xv.z; a1 += w2.y*xv.z; a2 += w2.z*xv.z; a3 += w2.w*xv.z;
        float4 w3 = *(const float4*)(wbase + (k+3)*16);
        a0 += w3.x*xv.w; a1 += w3.y*xv.w; a2 += w3.z*xv.w; a3 += w3.w*xv.w;
    }
}

// ---------------- grid barrier (sense reversal) ----------------
#define GRID_BAR()                                                        \
    do {                                                                  \
        __threadfence();                                                  \
        __syncthreads();                                                  \
        if (tid == 0) {                                                   \
            unsigned s = s_sense ^ 1u; s_sense = s;                       \
            if (atomicAdd(&d_bar_count, 1u) == NBLK - 1u) {               \
                d_bar_count = 0u;                                         \
                __threadfence();                                          \
                d_bar_sense = s;                                          \
            } else {                                                      \
                while (d_bar_sense != s) { __nanosleep(64); }             \
            }                                                             \
        }                                                                 \
        __syncthreads();                                                  \
    } while (0)

// ---------------- persistent main kernel: both scans ----------------
__global__ void __launch_bounds__(256, 1)
main_scan(const float* __restrict__ strks,
          const float* __restrict__ sents_m,
          const float* __restrict__ onehots,
          const float* __restrict__ Wsw,
          const float* __restrict__ bsw)
{
    __shared__ float xsm[64*XP];
    __shared__ float wsm[64*16];
    __shared__ float gsm[64*16];
    __shared__ float shh[512];
    __shared__ float s_pa[10], s_pb[10], s_pk[10], s_phi[64];
    __shared__ unsigned s_sense;

    const int tid = threadIdx.x;
    const int bb  = blockIdx.x;
    if (tid == 0) s_sense = 0u;
    __syncthreads();

    const int rq = tid >> 6;      // 0..3: gate index; rows rq*4..rq*4+3
    const int b  = tid & 63;      // batch column

    // ================= phase 1: LSTM1 + attention =================
    for (int t = 0; t < Tt; t++) {
        float a0 = d_b1p[bb*16 + rq*4 + 0];
        float a1 = d_b1p[bb*16 + rq*4 + 1];
        float a2 = d_b1p[bb*16 + rq*4 + 2];
        float a3 = d_b1p[bb*16 + rq*4 + 3];

        for (int ti = 0; ti < 9; ti++) {
            *(float4*)&wsm[tid*4] = *(const float4*)&d_P1[bb*9216 + ti*1024 + tid*4];
            if (ti == 0) {
                for (int i = tid; i < 4096; i += 256) {
                    int b2 = i >> 6, kk = i & 63;
                    float v = 0.f;
                    if (kk < 3)       v = strks[(b2*Tt + t)*3 + kk];
                    else if (kk < 63) v = __ldcg(&d_wbuf[b2*60 + kk - 3]);
                    xsm[b2*XP + kk] = v;
                }
            } else {
                for (int i = tid; i < 1024; i += 256) {
                    int b2 = i >> 4, k4 = (i & 15) << 2;
                    float4 v;
                    if (t > 0) v = *(const float4*)&d_hid1[(b2*Tt + t - 1)*512 + (ti-1)*64 + k4];
                    else       v = make_float4(0.f, 0.f, 0.f, 0.f);
                    *(float4*)&xsm[b2*XP + k4] = v;
                }
            }
            __syncthreads();
            tile_mac(&xsm[b*XP], wsm + rq*4, a0, a1, a2, a3);
            __syncthreads();
        }

        gsm[b*16 + rq*4 + 0] = a0;
        gsm[b*16 + rq*4 + 1] = a1;
        gsm[b*16 + rq*4 + 2] = a2;
        gsm[b*16 + rq*4 + 3] = a3;
        __syncthreads();
        {
            int b2 = tid >> 2, uu = tid & 3;
            int u = bb*4 + uu;
            float ig = gsm[b2*16 +  0 + uu];
            float fg = gsm[b2*16 +  4 + uu];
            float gg = gsm[b2*16 +  8 + uu];
            float og = gsm[b2*16 + 12 + uu];
            float c = sigf(fg)*d_c1[b2*512 + u] + sigf(ig)*tanhf(gg);
            float h = sigf(og)*tanhf(c);
            d_c1[b2*512 + u] = c;
            d_hid1[(b2*Tt + t)*512 + u] = h;
        }
        GRID_BAR();

        // ---- attention: blocks 0..63 handle batch bb ----
        if (bb < 64) {
            for (int i = tid; i < 512; i += 256) shh[i] = d_hid1[(bb*Tt + t)*512 + i];
            __syncthreads();
            {
                int warp = tid >> 5, lane = tid & 31;
                for (int o = warp; o < 30; o += 8) {
                    const float* wr = &Wsw[o*512];
                    float s = 0.f;
                    for (int k2 = lane; k2 < 512; k2 += 32) s += wr[k2]*shh[k2];
                    #pragma unroll
                    for (int off = 16; off; off >>= 1) s += __shfl_down_sync(0xffffffffu, s, off);
                    if (lane == 0) {
                        s += bsw[o];
                        if (o < 10)      s_pa[o] = expf(s);
                        else if (o < 20) s_pb[o-10] = expf(s);
                        else {
                            float kn = d_kbuf[bb*10 + (o-20)] + expf(s);
                            s_pk[o-20] = kn;
                            d_kbuf[bb*10 + (o-20)] = kn;
                        }
                    }
                }
            }
            __syncthreads();
            if (tid < 64) {
                float uu = (float)tid, s = 0.f;
                #pragma unroll
                for (int j = 0; j < 10; j++) {
                    float d = s_pk[j] - uu;
                    s += s_pa[j]*expf(-s_pb[j]*d*d);
                }
                s_phi[tid] = s * sents_m[bb*64 + tid];
            }
            __syncthreads();
            if (tid < 60) {
                float s = 0.f;
                const float* oh = &onehots[bb*64*60 + tid];
                for (int u2 = 0; u2 < 64; u2++) s += s_phi[u2]*oh[u2*60];
                d_wbuf[bb*60 + tid] = s;
                d_win[(bb*Tt + t)*60 + tid] = s;
            }
        }
        GRID_BAR();
    }

    // ================= phase 2: LSTM2 =================
    for (int t = 0; t < Tt; t++) {
        float a0 = d_b2p[bb*16 + rq*4 + 0];
        float a1 = d_b2p[bb*16 + rq*4 + 1];
        float a2 = d_b2p[bb*16 + rq*4 + 2];
        float a3 = d_b2p[bb*16 + rq*4 + 3];

        for (int ti = 0; ti < 17; ti++) {
            *(float4*)&wsm[tid*4] = *(const float4*)&d_P2[bb*17408 + ti*1024 + tid*4];
            if (ti < 8) {
                for (int i = tid; i < 1024; i += 256) {
                    int b2 = i >> 4, k4 = (i & 15) << 2;
                    *(float4*)&xsm[b2*XP + k4] =
                        *(const float4*)&d_hid1[(b2*Tt + t)*512 + ti*64 + k4];
                }
            } else if (ti == 8) {
                for (int i = tid; i < 4096; i += 256) {
                    int b2 = i >> 6, kk = i & 63;
                    float v = 0.f;
                    if (kk < 3)       v = strks[(b2*Tt + t)*3 + kk];
                    else if (kk < 63) v = d_win[(b2*Tt + t)*60 + kk - 3];
                    xsm[b2*XP + kk] = v;
                }
            } else {
                for (int i = tid; i < 1024; i += 256) {
                    int b2 = i >> 4, k4 = (i & 15) << 2;
                    float4 v;
                    if (t > 0) v = *(const float4*)&d_hid2[(b2*Tt + t - 1)*512 + (ti-9)*64 + k4];
                    else       v = make_float4(0.f, 0.f, 0.f, 0.f);
                    *(float4*)&xsm[b2*XP + k4] = v;
                }
            }
            __syncthreads();
            tile_mac(&xsm[b*XP], wsm + rq*4, a0, a1, a2, a3);
            __syncthreads();
        }

        gsm[b*16 + rq*4 + 0] = a0;
        gsm[b*16 + rq*4 + 1] = a1;
        gsm[b*16 + rq*4 + 2] = a2;
        gsm[b*16 + rq*4 + 3] = a3;
        __syncthreads();
        {
            int b2 = tid >> 2, uu = tid & 3;
            int u = bb*4 + uu;
            float ig = gsm[b2*16 +  0 + uu];
            float fg = gsm[b2*16 +  4 + uu];
            float gg = gsm[b2*16 +  8 + uu];
            float og = gsm[b2*16 + 12 + uu];
            float c = sigf(fg)*d_c2[b2*512 + u] + sigf(ig)*tanhf(gg);
            float h = sigf(og)*tanhf(c);
            d_c2[b2*512 + u] = c;
            d_hid2[(b2*Tt + t)*512 + u] = h;
        }
        GRID_BAR();
    }
}

// ---------------- MDN head (fully parallel) ----------------
__global__ void mdn_kernel(const float* __restrict__ bmdn, float* __restrict__ out)
{
    __shared__ float rows[8*1024];
    __shared__ float pbuf[8*128];
    const int tid  = threadIdx.x;
    const int row0 = blockIdx.x*8;

    for (int idx = tid; idx < 8*1024; idx += 256) {
        int rr = idx >> 10, k2 = idx & 1023;
        int bt = row0 + rr;
        rows[idx] = (k2 < 512) ? d_hid1[bt*512 + k2] : d_hid2[bt*512 + (k2-512)];
    }
    __syncthreads();

    const int o    = tid & 127;
    const int half = tid >> 7;
    if (o < MDNO) {
        float acc[4];
        float bbv = bmdn[o];
        #pragma unroll
        for (int i = 0; i < 4; i++) acc[i] = bbv;
        const float* wr = &d_Weff[o*1024];
        for (int k2 = 0; k2 < 1024; k2 += 4) {
            float4 w = *(const float4*)(wr + k2);
            #pragma unroll
            for (int i = 0; i < 4; i++) {
                const float* x = &rows[(half*4 + i)*1024 + k2];
                acc[i] += w.x*x[0] + w.y*x[1] + w.z*x[2] + w.w*x[3];
            }
        }
        #pragma unroll
        for (int i = 0; i < 4; i++) pbuf[(half*4 + i)*128 + o] = acc[i];
    }
    __syncthreads();

    const int warp = tid >> 5, lane = tid & 31;
    const int bt = row0 + warp;
    const float* p = &pbuf[warp*128];

    float v = (lane < 20) ? p[lane] : -1e30f;
    float mx = v;
    #pragma unroll
    for (int off = 16; off; off >>= 1) mx = fmaxf(mx, __shfl_xor_sync(0xffffffffu, mx, off));
    float e = (lane < 20) ? expf(v - mx) : 0.f;
    float sum = e;
    #pragma unroll
    for (int off = 16; off; off >>= 1) sum += __shfl_xor_sync(0xffffffffu, sum, off);

    if (lane < 20) {
        float* base = out + BT;
        base[            bt*20 + lane] = e / sum;               // weights
        base[1*BT*20  +  bt*20 + lane] = p[20 + lane];          // mu1
        base[2*BT*20  +  bt*20 + lane] = p[40 + lane];          // mu2
        base[3*BT*20  +  bt*20 + lane] = expf(p[60 + lane]);    // s1
        base[4*BT*20  +  bt*20 + lane] = expf(p[80 + lane]);    // s2
        base[5*BT*20  +  bt*20 + lane] = tanhf(p[100 + lane]);  // rho
    }
    if (lane == 20) out[bt] = 1.f/(1.f + expf(-p[120]));        // eos
}

// ---------------- launch (7 graph nodes total) ----------------
extern "C" void kernel_launch(void* const* d_in, const int* in_sizes, int n_in,
                              void* d_out, int out_size)
{
    const float* strks   = (const float*)d_in[0];
    // d_in[1] strks_m: unused; d_in[2] sents (int64): unused
    const float* sents_m = (const float*)d_in[3];
    const float* onehots = (const float*)d_in[4];
    const float* w_prev  = (const float*)d_in[5];
    const float* Wih1    = (const float*)d_in[6];
    const float* Whh1    = (const float*)d_in[7];
    const float* bih1    = (const float*)d_in[8];
    const float* bhh1    = (const float*)d_in[9];
    const float* Wih2    = (const float*)d_in[10];
    const float* Whh2    = (const float*)d_in[11];
    const float* bih2    = (const float*)d_in[12];
    const float* bhh2    = (const float*)d_in[13];
    const float* Wsw     = (const float*)d_in[14];
    const float* bsw     = (const float*)d_in[15];
    const float* Wmdn    = (const float*)d_in[16];
    const float* bmdn    = (const float*)d_in[17];
    float* out = (float*)d_out;

    prep_pack1<<<(NBLK*576*16  + 255)/256, 256>>>(Wih1, Whh1);
    prep_pack2<<<(NBLK*1088*16 + 255)/256, 256>>>(Wih2, Whh2);
    prep_bias <<<(G4 + 255)/256, 256>>>(bih1, bhh1, bih2, bhh2);
    prep_weff <<<(MDNO*1024 + 255)/256, 256>>>(Wmdn);
    init_state<<<(Bz*Hh + 255)/256, 256>>>(w_prev);

    main_scan<<<NBLK, 256>>>(strks, sents_m, onehots, Wsw, bsw);
    mdn_kernel<<<BT/8, 256>>>(bmdn, out);
}

// round 7
// speedup vs baseline: 1.9588x; 1.9588x over previous
#include <cuda_runtime.h>
#include <math.h>

// ---------------- problem constants ----------------
#define Bz   64
#define Tt   800
#define Hh   512
#define Kk   10
#define SENT 60
#define G4   2048            // 4*H
#define BT   (Bz*Tt)         // 51200
#define MDNO 121             // 1 + 6*M
#define NBLK 128             // persistent grid (<=148 SMs -> co-resident)

// dynamic smem layout (floats)
#define XP1  580             // phase1 x pitch (576 cols), 580%32==4 -> conflict-free LDS.128
#define XP2  548             // phase2 x pitch (544 cols per half), 548%32==4
#define SM_W 0               // 17408 floats (phase2 weights; phase1 uses first 9216)
#define SM_X 17408           // 37120 floats (64 * 580)
#define SM_G (17408+37120)   // 54528: gate staging 64*17 = 1088
#define SM_A (SM_G+1088)     // 55616: attention scratch (640)
#define SM_TOT (SM_A+640)    // 56256 floats = 225024 bytes

// ---------------- persistent device scratch (no allocations) ----------------
__device__ float d_hid1[BT*Hh];
__device__ float d_hid2[BT*Hh];
__device__ float d_win [BT*SENT];
__device__ float d_c1  [Bz*Hh];
__device__ float d_c2  [Bz*Hh];
__device__ float d_kbuf[Bz*Kk];
__device__ float d_wbuf[Bz*SENT];

// per-block packed weights: [block][k][16 rows], row = gate*4 + unit
__device__ float d_P1 [NBLK*576*16];
__device__ float d_P2 [NBLK*1088*16];
__device__ float d_b1p[G4];
__device__ float d_b2p[G4];
__device__ float d_Weff[MDNO*1024];

__device__ unsigned          d_bar_count;
__device__ volatile unsigned d_bar_sense;

__device__ __forceinline__ float sigf(float x) { return 1.f/(1.f+expf(-x)); }

// ---------------- prep kernels ----------------
__global__ void prep_pack1(const float* __restrict__ Wih1, const float* __restrict__ Whh1) {
    int idx = blockIdx.x*blockDim.x + threadIdx.x;
    if (idx >= NBLK*576*16) return;
    int bb = idx / 9216, rem = idx % 9216;
    int k = rem >> 4, rr = rem & 15;
    int gate = rr >> 2, uu = rr & 3;
    int grow = gate*512 + bb*4 + uu;
    float v;
    if (k < 64) v = (k < 63) ? Wih1[grow*63 + k] : 0.f;   // [strk3|win60|pad]
    else        v = Whh1[grow*512 + (k-64)];
    d_P1[idx] = v;
}

__global__ void prep_pack2(const float* __restrict__ Wih2, const float* __restrict__ Whh2) {
    int idx = blockIdx.x*blockDim.x + threadIdx.x;
    if (idx >= NBLK*1088*16) return;
    int bb = idx / 17408, rem = idx % 17408;
    int k = rem >> 4, rr = rem & 15;
    int gate = rr >> 2, uu = rr & 3;
    int grow = gate*512 + bb*4 + uu;
    float v;
    if      (k < 512)  v = Wih2[grow*575 + 3 + k];
    else if (k < 515)  v = Wih2[grow*575 + (k-512)];
    else if (k < 575)  v = Wih2[grow*575 + k];
    else if (k == 575) v = 0.f;
    else               v = Whh2[grow*512 + (k-576)];
    d_P2[idx] = v;
}

// fused: bias pack + Weff fold + state init + barrier init
__global__ void prep_misc(const float* __restrict__ bih1, const float* __restrict__ bhh1,
                          const float* __restrict__ bih2, const float* __restrict__ bhh2,
                          const float* __restrict__ Wmdn, const float* __restrict__ w_prev) {
    int idx = blockIdx.x*blockDim.x + threadIdx.x;
    if (idx < MDNO*1024) {
        int o = idx >> 10, k = idx & 1023;
        float v = Wmdn[o*1536 + k];
        if (k >= 512) v += Wmdn[o*1536 + k + 512];
        d_Weff[idx] = v;
    }
    if (idx < G4) {
        int bb = idx >> 4, rr = idx & 15;
        int gate = rr >> 2, uu = rr & 3;
        int grow = gate*512 + bb*4 + uu;
        d_b1p[idx] = bih1[grow] + bhh1[grow];
        d_b2p[idx] = bih2[grow] + bhh2[grow];
    }
    if (idx < Bz*Hh) { d_c1[idx] = 0.f; d_c2[idx] = 0.f; }
    if (idx < Bz*Kk)   d_kbuf[idx] = 0.f;
    if (idx < Bz*SENT) d_wbuf[idx] = w_prev[idx];
    if (idx == 0) { d_bar_count = 0u; d_bar_sense = 0u; }
}

// ---------------- grid barrier (sense reversal) ----------------
#define GRID_BAR()                                                        \
    do {                                                                  \
        __threadfence();                                                  \
        __syncthreads();                                                  \
        if (tid == 0) {                                                   \
            unsigned s = s_sense ^ 1u; s_sense = s;                       \
            if (atomicAdd(&d_bar_count, 1u) == NBLK - 1u) {               \
                d_bar_count = 0u;                                         \
                __threadfence();                                          \
                d_bar_sense = s;                                          \
            } else {                                                      \
                while (d_bar_sense != s) { __nanosleep(32); }             \
            }                                                             \
        }                                                                 \
        __syncthreads();                                                  \
    } while (0)

// ---------------- MAC over a k-range (x and w both in smem) ----------------
__device__ __forceinline__ void mac_k(const float* __restrict__ xr,
                                      const float* __restrict__ wr, int cnt,
                                      float& a0, float& a1, float& a2, float& a3)
{
    #pragma unroll 8
    for (int k = 0; k < cnt; k += 4) {
        float4 xv = *(const float4*)(xr + k);
        float4 w0 = *(const float4*)(wr + (k+0)*16);
        a0 = fmaf(w0.x, xv.x, a0); a1 = fmaf(w0.y, xv.x, a1);
        a2 = fmaf(w0.z, xv.x, a2); a3 = fmaf(w0.w, xv.x, a3);
        float4 w1 = *(const float4*)(wr + (k+1)*16);
        a0 = fmaf(w1.x, xv.y, a0); a1 = fmaf(w1.y, xv.y, a1);
        a2 = fmaf(w1.z, xv.y, a2); a3 = fmaf(w1.w, xv.y, a3);
        float4 w2 = *(const float4*)(wr + (k+2)*16);
        a0 = fmaf(w2.x, xv.z, a0); a1 = fmaf(w2.y, xv.z, a1);
        a2 = fmaf(w2.z, xv.z, a2); a3 = fmaf(w2.w, xv.z, a3);
        float4 w3 = *(const float4*)(wr + (k+3)*16);
        a0 = fmaf(w3.x, xv.w, a0); a1 = fmaf(w3.y, xv.w, a1);
        a2 = fmaf(w3.z, xv.w, a2); a3 = fmaf(w3.w, xv.w, a3);
    }
}

// ---------------- persistent main kernel ----------------
extern __shared__ float sm[];

__global__ void __launch_bounds__(256, 1)
main_scan(const float* __restrict__ strks,
          const float* __restrict__ sents_m,
          const float* __restrict__ onehots,
          const float* __restrict__ Wsw,
          const float* __restrict__ bsw)
{
    __shared__ unsigned s_sense;
    float* W  = sm + SM_W;
    float* X  = sm + SM_X;
    float* Gm = sm + SM_G;
    float* At = sm + SM_A;     // shh 512 | pa@512 | pb@524 | pk@536 | phi@552

    const int tid = threadIdx.x;
    const int bb  = blockIdx.x;
    if (tid == 0) s_sense = 0u;

    const int rq = tid >> 6;   // gate 0..3 -> rows rq*4..rq*4+3
    const int b  = tid & 63;   // batch column

    // ================= phase 1 =================
    // weights resident for whole phase
    {
        const float4* src = (const float4*)(d_P1 + bb*9216);
        for (int i = tid; i < 2304; i += 256) ((float4*)W)[i] = src[i];
    }
    const float bs10 = d_b1p[bb*16 + rq*4 + 0];
    const float bs11 = d_b1p[bb*16 + rq*4 + 1];
    const float bs12 = d_b1p[bb*16 + rq*4 + 2];
    const float bs13 = d_b1p[bb*16 + rq*4 + 3];

    // pre-fill X for t=0: strk | wbuf | pad | zeros
    for (int i = tid; i < 4096; i += 256) {
        int b2 = i >> 6, kk = i & 63;
        float v = 0.f;
        if (kk < 3)       v = strks[(b2*Tt + 0)*3 + kk];
        else if (kk < 63) v = __ldcg(&d_wbuf[b2*60 + kk - 3]);
        X[b2*XP1 + kk] = v;
    }
    for (int i = tid; i < 64*128; i += 256) {
        int b2 = i >> 7, kq = i & 127;
        *(float4*)&X[b2*XP1 + 64 + kq*4] = make_float4(0.f,0.f,0.f,0.f);
    }
    __syncthreads();

    for (int t = 0; t < Tt; t++) {
        float a0 = bs10, a1 = bs11, a2 = bs12, a3 = bs13;
        mac_k(&X[b*XP1], &W[rq*4], 576, a0, a1, a2, a3);

        Gm[b*17 + rq*4 + 0] = a0;
        Gm[b*17 + rq*4 + 1] = a1;
        Gm[b*17 + rq*4 + 2] = a2;
        Gm[b*17 + rq*4 + 3] = a3;
        __syncthreads();
        {
            int b2 = tid >> 2, uu = tid & 3;
            int u = bb*4 + uu;
            float ig = Gm[b2*17 +  0 + uu];
            float fg = Gm[b2*17 +  4 + uu];
            float gg = Gm[b2*17 +  8 + uu];
            float og = Gm[b2*17 + 12 + uu];
            float c = sigf(fg)*d_c1[b2*512 + u] + sigf(ig)*tanhf(gg);
            float h = sigf(og)*tanhf(c);
            d_c1[b2*512 + u] = c;
            d_hid1[(b2*Tt + t)*512 + u] = h;
        }
        GRID_BAR();   // h1(t) visible everywhere

        // attention on blocks 0..63 (overlaps other blocks' fills)
        if (bb < 64) {
            float* shh = At; float* pa = At+512; float* pb = At+524;
            float* pk = At+536; float* phi = At+552;
            for (int i = tid; i < 512; i += 256) shh[i] = __ldcg(&d_hid1[(bb*Tt + t)*512 + i]);
            __syncthreads();
            {
                int warp = tid >> 5, lane = tid & 31;
                for (int o = warp; o < 30; o += 8) {
                    const float* wr = &Wsw[o*512];
                    float s = 0.f;
                    for (int k2 = lane; k2 < 512; k2 += 32) s += wr[k2]*shh[k2];
                    #pragma unroll
                    for (int off = 16; off; off >>= 1) s += __shfl_down_sync(0xffffffffu, s, off);
                    if (lane == 0) {
                        s += bsw[o];
                        if (o < 10)      pa[o] = expf(s);
                        else if (o < 20) pb[o-10] = expf(s);
                        else {
                            float kn = d_kbuf[bb*10 + (o-20)] + expf(s);
                            pk[o-20] = kn;
                            d_kbuf[bb*10 + (o-20)] = kn;
                        }
                    }
                }
            }
            __syncthreads();
            if (tid < 64) {
                float uu = (float)tid, s = 0.f;
                #pragma unroll
                for (int j = 0; j < 10; j++) {
                    float d = pk[j] - uu;
                    s += pa[j]*expf(-pb[j]*d*d);
                }
                phi[tid] = s * sents_m[bb*64 + tid];
            }
            __syncthreads();
            if (tid < 60) {
                float s = 0.f;
                const float* oh = &onehots[bb*64*60 + tid];
                for (int u2 = 0; u2 < 64; u2++) s += phi[u2]*oh[u2*60];
                d_wbuf[bb*60 + tid] = s;
                d_win[(bb*Tt + t)*60 + tid] = s;
            }
        }

        if (t + 1 < Tt) {
            // recurrent fill (needs only h1(t), ready) + strk(t+1)
            for (int i = tid; i < 64*128; i += 256) {
                int b2 = i >> 7, kq = i & 127;
                *(float4*)&X[b2*XP1 + 64 + kq*4] =
                    __ldcg((const float4*)&d_hid1[(b2*Tt + t)*512 + kq*4]);
            }
            for (int i = tid; i < 192; i += 256) {
                int b2 = i / 3, kk = i % 3;
                X[b2*XP1 + kk] = strks[(b2*Tt + t + 1)*3 + kk];
            }
        }
        GRID_BAR();   // wbuf(t) visible everywhere

        if (t + 1 < Tt) {
            for (int i = tid; i < 3840; i += 256) {
                int b2 = i / 60, kk = i % 60;
                X[b2*XP1 + 3 + kk] = __ldcg(&d_wbuf[b2*60 + kk]);
            }
        }
        __syncthreads();
    }

    // ================= phase 2 =================
    {
        const float4* src = (const float4*)(d_P2 + bb*17408);
        for (int i = tid; i < 4352; i += 256) ((float4*)W)[i] = src[i];
    }
    const float bs20 = d_b2p[bb*16 + rq*4 + 0];
    const float bs21 = d_b2p[bb*16 + rq*4 + 1];
    const float bs22 = d_b2p[bb*16 + rq*4 + 2];
    const float bs23 = d_b2p[bb*16 + rq*4 + 3];
    __syncthreads();

    for (int t = 0; t < Tt; t++) {
        float a0 = bs20, a1 = bs21, a2 = bs22, a3 = bs23;

        // half A: k 0..543 = hid1(t)[0..511] | strk(3) | win[0..28]
        for (int i = tid; i < 64*128; i += 256) {
            int b2 = i >> 7, kq = i & 127;
            *(float4*)&X[b2*XP2 + kq*4] =
                __ldcg((const float4*)&d_hid1[(b2*Tt + t)*512 + kq*4]);
        }
        for (int i = tid; i < 2048; i += 256) {
            int b2 = i >> 5, kk = i & 31;
            int k = 512 + kk;
            float v = (k < 515) ? strks[(b2*Tt + t)*3 + (k-512)]
                                : __ldcg(&d_win[(b2*Tt + t)*60 + (k-515)]);
            X[b2*XP2 + 512 + kk] = v;
        }
        __syncthreads();
        mac_k(&X[b*XP2], &W[rq*4], 544, a0, a1, a2, a3);
        __syncthreads();

        // half B: k 544..1087 = win[29..59] | pad | hid2(t-1)
        for (int i = tid; i < 2048; i += 256) {
            int b2 = i >> 5, kk = i & 31;
            int k = 544 + kk;
            float v = (k < 575) ? __ldcg(&d_win[(b2*Tt + t)*60 + (k-515)]) : 0.f;
            X[b2*XP2 + kk] = v;
        }
        for (int i = tid; i < 64*128; i += 256) {
            int b2 = i >> 7, kq = i & 127;
            float4 v = (t > 0) ? __ldcg((const float4*)&d_hid2[(b2*Tt + t - 1)*512 + kq*4])
                               : make_float4(0.f,0.f,0.f,0.f);
            *(float4*)&X[b2*XP2 + 32 + kq*4] = v;
        }
        __syncthreads();
        mac_k(&X[b*XP2], &W[544*16 + rq*4], 544, a0, a1, a2, a3);

        Gm[b*17 + rq*4 + 0] = a0;
        Gm[b*17 + rq*4 + 1] = a1;
        Gm[b*17 + rq*4 + 2] = a2;
        Gm[b*17 + rq*4 + 3] = a3;
        __syncthreads();
        {
            int b2 = tid >> 2, uu = tid & 3;
            int u = bb*4 + uu;
            float ig = Gm[b2*17 +  0 + uu];
            float fg = Gm[b2*17 +  4 + uu];
            float gg = Gm[b2*17 +  8 + uu];
            float og = Gm[b2*17 + 12 + uu];
            float c = sigf(fg)*d_c2[b2*512 + u] + sigf(ig)*tanhf(gg);
            float h = sigf(og)*tanhf(c);
            d_c2[b2*512 + u] = c;
            d_hid2[(b2*Tt + t)*512 + u] = h;
        }
        GRID_BAR();   // h2(t) visible everywhere
    }
}

// ---------------- MDN head ----------------
__global__ void mdn_kernel(const float* __restrict__ bmdn, float* __restrict__ out)
{
    __shared__ float rows[8*1024];
    __shared__ float pbuf[8*128];
    const int tid  = threadIdx.x;
    const int row0 = blockIdx.x*8;

    for (int idx = tid; idx < 8*1024; idx += 256) {
        int rr = idx >> 10, k2 = idx & 1023;
        int bt = row0 + rr;
        rows[idx] = (k2 < 512) ? d_hid1[bt*512 + k2] : d_hid2[bt*512 + (k2-512)];
    }
    __syncthreads();

    const int o    = tid & 127;
    const int half = tid >> 7;
    if (o < MDNO) {
        float acc[4];
        float bbv = bmdn[o];
        #pragma unroll
        for (int i = 0; i < 4; i++) acc[i] = bbv;
        const float* wr = &d_Weff[o*1024];
        for (int k2 = 0; k2 < 1024; k2 += 4) {
            float4 w = *(const float4*)(wr + k2);
            #pragma unroll
            for (int i = 0; i < 4; i++) {
                const float* x = &rows[(half*4 + i)*1024 + k2];
                acc[i] += w.x*x[0] + w.y*x[1] + w.z*x[2] + w.w*x[3];
            }
        }
        #pragma unroll
        for (int i = 0; i < 4; i++) pbuf[(half*4 + i)*128 + o] = acc[i];
    }
    __syncthreads();

    const int warp = tid >> 5, lane = tid & 31;
    const int bt = row0 + warp;
    const float* p = &pbuf[warp*128];

    float v = (lane < 20) ? p[lane] : -1e30f;
    float mx = v;
    #pragma unroll
    for (int off = 16; off; off >>= 1) mx = fmaxf(mx, __shfl_xor_sync(0xffffffffu, mx, off));
    float e = (lane < 20) ? expf(v - mx) : 0.f;
    float sum = e;
    #pragma unroll
    for (int off = 16; off; off >>= 1) sum += __shfl_xor_sync(0xffffffffu, sum, off);

    if (lane < 20) {
        float* base = out + BT;
        base[            bt*20 + lane] = e / sum;
        base[1*BT*20  +  bt*20 + lane] = p[20 + lane];
        base[2*BT*20  +  bt*20 + lane] = p[40 + lane];
        base[3*BT*20  +  bt*20 + lane] = expf(p[60 + lane]);
        base[4*BT*20  +  bt*20 + lane] = expf(p[80 + lane]);
        base[5*BT*20  +  bt*20 + lane] = tanhf(p[100 + lane]);
    }
    if (lane == 20) out[bt] = 1.f/(1.f + expf(-p[120]));
}

// ---------------- launch (5 graph nodes) ----------------
extern "C" void kernel_launch(void* const* d_in, const int* in_sizes, int n_in,
                              void* d_out, int out_size)
{
    const float* strks   = (const float*)d_in[0];
    const float* sents_m = (const float*)d_in[3];
    const float* onehots = (const float*)d_in[4];
    const float* w_prev  = (const float*)d_in[5];
    const float* Wih1    = (const float*)d_in[6];
    const float* Whh1    = (const float*)d_in[7];
    const float* bih1    = (const float*)d_in[8];
    const float* bhh1    = (const float*)d_in[9];
    const float* Wih2    = (const float*)d_in[10];
    const float* Whh2    = (const float*)d_in[11];
    const float* bih2    = (const float*)d_in[12];
    const float* bhh2    = (const float*)d_in[13];
    const float* Wsw     = (const float*)d_in[14];
    const float* bsw     = (const float*)d_in[15];
    const float* Wmdn    = (const float*)d_in[16];
    const float* bmdn    = (const float*)d_in[17];
    float* out = (float*)d_out;

    static int smem_set = 0;
    if (!smem_set) {
        cudaFuncSetAttribute(main_scan, cudaFuncAttributeMaxDynamicSharedMemorySize,
                             SM_TOT*sizeof(float));
        smem_set = 1;
    }

    prep_pack1<<<(NBLK*576*16  + 255)/256, 256>>>(Wih1, Whh1);
    prep_pack2<<<(NBLK*1088*16 + 255)/256, 256>>>(Wih2, Whh2);
    prep_misc <<<(MDNO*1024 + 255)/256, 256>>>(bih1, bhh1, bih2, bhh2, Wmdn, w_prev);

    main_scan<<<NBLK, 256, SM_TOT*sizeof(float)>>>(strks, sents_m, onehots, Wsw, bsw);
    mdn_kernel<<<BT/8, 256>>>(bmdn, out);
}

// round 8
// speedup vs baseline: 2.1341x; 1.0895x over previous
#include <cuda_runtime.h>
#include <math.h>

// ---------------- problem constants ----------------
#define Bz   64
#define Tt   800
#define Hh   512
#define Kk   10
#define SENT 60
#define G4   2048            // 4*H
#define BT   (Bz*Tt)         // 51200
#define MDNO 121             // 1 + 6*M
#define NBLK 128             // persistent grid (<=148 SMs -> co-resident)
#define THR  512             // 16 warps: 2 warp-groups split K

// dynamic smem layout (floats)
#define XP1  580             // phase1 x pitch (576 cols), 580%32==4 -> conflict-free LDS.128
#define XP2  548             // phase2 x pitch (544 cols per half), 548%32==4
#define SM_W 0               // 17408 floats (phase2 weights; phase1 uses first 9216)
#define SM_X 17408           // 37120 floats (64 * 580)
#define SM_G (17408+37120)   // 54528: gate partials 2 * 64*17 = 2176
#define SM_A (SM_G+2176)     // 56704: attention scratch (640)
#define SM_TOT (SM_A+640)    // 57344 floats = 229376 bytes

// ---------------- persistent device scratch (no allocations) ----------------
__device__ float d_hid1[BT*Hh];
__device__ float d_hid2[BT*Hh];
__device__ float d_win [BT*SENT];
__device__ float d_c1  [Bz*Hh];
__device__ float d_c2  [Bz*Hh];
__device__ float d_kbuf[Bz*Kk];
__device__ float d_wbuf[Bz*SENT];

// per-block packed weights: [block][k][16 rows], row = gate*4 + unit
__device__ float d_P1 [NBLK*576*16];
__device__ float d_P2 [NBLK*1088*16];
__device__ float d_b1p[G4];
__device__ float d_b2p[G4];
__device__ float d_Weff[MDNO*1024];

__device__ unsigned          d_bar_count;
__device__ volatile unsigned d_bar_sense;

__device__ __forceinline__ float sigf(float x) { return 1.f/(1.f+expf(-x)); }

// ---------------- prep kernels ----------------
__global__ void prep_pack1(const float* __restrict__ Wih1, const float* __restrict__ Whh1) {
    int idx = blockIdx.x*blockDim.x + threadIdx.x;
    if (idx >= NBLK*576*16) return;
    int bb = idx / 9216, rem = idx % 9216;
    int k = rem >> 4, rr = rem & 15;
    int gate = rr >> 2, uu = rr & 3;
    int grow = gate*512 + bb*4 + uu;
    float v;
    if (k < 64) v = (k < 63) ? Wih1[grow*63 + k] : 0.f;   // [strk3|win60|pad]
    else        v = Whh1[grow*512 + (k-64)];
    d_P1[idx] = v;
}

__global__ void prep_pack2(const float* __restrict__ Wih2, const float* __restrict__ Whh2) {
    int idx = blockIdx.x*blockDim.x + threadIdx.x;
    if (idx >= NBLK*1088*16) return;
    int bb = idx / 17408, rem = idx % 17408;
    int k = rem >> 4, rr = rem & 15;
    int gate = rr >> 2, uu = rr & 3;
    int grow = gate*512 + bb*4 + uu;
    float v;
    if      (k < 512)  v = Wih2[grow*575 + 3 + k];
    else if (k < 515)  v = Wih2[grow*575 + (k-512)];
    else if (k < 575)  v = Wih2[grow*575 + k];
    else if (k == 575) v = 0.f;
    else               v = Whh2[grow*512 + (k-576)];
    d_P2[idx] = v;
}

// fused: bias pack + Weff fold + state init + barrier init
__global__ void prep_misc(const float* __restrict__ bih1, const float* __restrict__ bhh1,
                          const float* __restrict__ bih2, const float* __restrict__ bhh2,
                          const float* __restrict__ Wmdn, const float* __restrict__ w_prev) {
    int idx = blockIdx.x*blockDim.x + threadIdx.x;
    if (idx < MDNO*1024) {
        int o = idx >> 10, k = idx & 1023;
        float v = Wmdn[o*1536 + k];
        if (k >= 512) v += Wmdn[o*1536 + k + 512];
        d_Weff[idx] = v;
    }
    if (idx < G4) {
        int bb = idx >> 4, rr = idx & 15;
        int gate = rr >> 2, uu = rr & 3;
        int grow = gate*512 + bb*4 + uu;
        d_b1p[idx] = bih1[grow] + bhh1[grow];
        d_b2p[idx] = bih2[grow] + bhh2[grow];
    }
    if (idx < Bz*Hh) { d_c1[idx] = 0.f; d_c2[idx] = 0.f; }
    if (idx < Bz*Kk)   d_kbuf[idx] = 0.f;
    if (idx < Bz*SENT) d_wbuf[idx] = w_prev[idx];
    if (idx == 0) { d_bar_count = 0u; d_bar_sense = 0u; }
}

// ---------------- grid barrier (sense reversal) ----------------
#define GRID_BAR()                                                        \
    do {                                                                  \
        __threadfence();                                                  \
        __syncthreads();                                                  \
        if (tid == 0) {                                                   \
            unsigned s = s_sense ^ 1u; s_sense = s;                       \
            if (atomicAdd(&d_bar_count, 1u) == NBLK - 1u) {               \
                d_bar_count = 0u;                                         \
                __threadfence();                                          \
                d_bar_sense = s;                                          \
            } else {                                                      \
                while (d_bar_sense != s) { __nanosleep(32); }             \
            }                                                             \
        }                                                                 \
        __syncthreads();                                                  \
    } while (0)

// ---------------- MAC over a k-range (x and w both in smem) ----------------
__device__ __forceinline__ void mac_k(const float* __restrict__ xr,
                                      const float* __restrict__ wr, int cnt,
                                      float& a0, float& a1, float& a2, float& a3)
{
    #pragma unroll 8
    for (int k = 0; k < cnt; k += 4) {
        float4 xv = *(const float4*)(xr + k);
        float4 w0 = *(const float4*)(wr + (k+0)*16);
        a0 = fmaf(w0.x, xv.x, a0); a1 = fmaf(w0.y, xv.x, a1);
        a2 = fmaf(w0.z, xv.x, a2); a3 = fmaf(w0.w, xv.x, a3);
        float4 w1 = *(const float4*)(wr + (k+1)*16);
        a0 = fmaf(w1.x, xv.y, a0); a1 = fmaf(w1.y, xv.y, a1);
        a2 = fmaf(w1.z, xv.y, a2); a3 = fmaf(w1.w, xv.y, a3);
        float4 w2 = *(const float4*)(wr + (k+2)*16);
        a0 = fmaf(w2.x, xv.z, a0); a1 = fmaf(w2.y, xv.z, a1);
        a2 = fmaf(w2.z, xv.z, a2); a3 = fmaf(w2.w, xv.z, a3);
        float4 w3 = *(const float4*)(wr + (k+3)*16);
        a0 = fmaf(w3.x, xv.w, a0); a1 = fmaf(w3.y, xv.w, a1);
        a2 = fmaf(w3.z, xv.w, a2); a3 = fmaf(w3.w, xv.w, a3);
    }
}

// ---------------- persistent main kernel ----------------
extern __shared__ float sm[];

__global__ void __launch_bounds__(THR, 1)
main_scan(const float* __restrict__ strks,
          const float* __restrict__ sents_m,
          const float* __restrict__ onehots,
          const float* __restrict__ Wsw,
          const float* __restrict__ bsw)
{
    __shared__ unsigned s_sense;
    float* W  = sm + SM_W;
    float* X  = sm + SM_X;
    float* Gm = sm + SM_G;     // [2][64*17] partials per warp-group
    float* At = sm + SM_A;     // shh 512 | pa@512 | pb@524 | pk@536 | phi@552

    const int tid = threadIdx.x;
    const int bb  = blockIdx.x;
    if (tid == 0) s_sense = 0u;

    const int wg = tid >> 8;        // warp-group: 0 = low K, 1 = high K
    const int rq = (tid >> 6) & 3;  // gate 0..3 -> rows rq*4..rq*4+3
    const int b  = tid & 63;        // batch column

    // ================= phase 1 =================
    {
        const float4* src = (const float4*)(d_P1 + bb*9216);
        for (int i = tid; i < 2304; i += THR) ((float4*)W)[i] = src[i];
    }
    // wg0 carries the bias, wg1 starts at 0
    const float bs10 = wg ? 0.f : d_b1p[bb*16 + rq*4 + 0];
    const float bs11 = wg ? 0.f : d_b1p[bb*16 + rq*4 + 1];
    const float bs12 = wg ? 0.f : d_b1p[bb*16 + rq*4 + 2];
    const float bs13 = wg ? 0.f : d_b1p[bb*16 + rq*4 + 3];

    // pre-fill X for t=0
    for (int i = tid; i < 4096; i += THR) {
        int b2 = i >> 6, kk = i & 63;
        float v = 0.f;
        if (kk < 3)       v = strks[(b2*Tt + 0)*3 + kk];
        else if (kk < 63) v = __ldcg(&d_wbuf[b2*60 + kk - 3]);
        X[b2*XP1 + kk] = v;
    }
    for (int i = tid; i < 64*128; i += THR) {
        int b2 = i >> 7, kq = i & 127;
        *(float4*)&X[b2*XP1 + 64 + kq*4] = make_float4(0.f,0.f,0.f,0.f);
    }
    __syncthreads();

    for (int t = 0; t < Tt; t++) {
        float a0 = bs10, a1 = bs11, a2 = bs12, a3 = bs13;
        // K split: wg0 -> k 0..287, wg1 -> k 288..575
        mac_k(&X[b*XP1 + wg*288], &W[wg*288*16 + rq*4], 288, a0, a1, a2, a3);

        float* g = Gm + wg*1088 + b*17 + rq*4;
        g[0] = a0; g[1] = a1; g[2] = a2; g[3] = a3;
        __syncthreads();
        if (tid < 256) {
            int b2 = tid >> 2, uu = tid & 3;
            int u = bb*4 + uu;
            float ig = Gm[b2*17 +  0 + uu] + Gm[1088 + b2*17 +  0 + uu];
            float fg = Gm[b2*17 +  4 + uu] + Gm[1088 + b2*17 +  4 + uu];
            float gg = Gm[b2*17 +  8 + uu] + Gm[1088 + b2*17 +  8 + uu];
            float og = Gm[b2*17 + 12 + uu] + Gm[1088 + b2*17 + 12 + uu];
            float c = sigf(fg)*d_c1[b2*512 + u] + sigf(ig)*tanhf(gg);
            float h = sigf(og)*tanhf(c);
            d_c1[b2*512 + u] = c;
            d_hid1[(b2*Tt + t)*512 + u] = h;
        }
        GRID_BAR();   // h1(t) visible everywhere

        // attention on blocks 0..63 (overlaps other blocks' fills)
        if (bb < 64) {
            float* shh = At; float* pa = At+512; float* pb = At+524;
            float* pk = At+536; float* phi = At+552;
            for (int i = tid; i < 512; i += THR) shh[i] = __ldcg(&d_hid1[(bb*Tt + t)*512 + i]);
            __syncthreads();
            {
                int warp = tid >> 5, lane = tid & 31;
                for (int o = warp; o < 30; o += 16) {
                    const float* wr = &Wsw[o*512];
                    float s = 0.f;
                    #pragma unroll 4
                    for (int k2 = lane; k2 < 512; k2 += 32) s += wr[k2]*shh[k2];
                    #pragma unroll
                    for (int off = 16; off; off >>= 1) s += __shfl_down_sync(0xffffffffu, s, off);
                    if (lane == 0) {
                        s += bsw[o];
                        if (o < 10)      pa[o] = expf(s);
                        else if (o < 20) pb[o-10] = expf(s);
                        else {
                            float kn = d_kbuf[bb*10 + (o-20)] + expf(s);
                            pk[o-20] = kn;
                            d_kbuf[bb*10 + (o-20)] = kn;
                        }
                    }
                }
            }
            __syncthreads();
            if (tid < 64) {
                float uu = (float)tid, s = 0.f;
                #pragma unroll
                for (int j = 0; j < 10; j++) {
                    float d = pk[j] - uu;
                    s += pa[j]*expf(-pb[j]*d*d);
                }
                phi[tid] = s * sents_m[bb*64 + tid];
            }
            __syncthreads();
            if (tid < 60) {
                float s = 0.f;
                const float* oh = &onehots[bb*64*60 + tid];
                for (int u2 = 0; u2 < 64; u2++) s += phi[u2]*oh[u2*60];
                d_wbuf[bb*60 + tid] = s;
                d_win[(bb*Tt + t)*60 + tid] = s;
            }
        }

        if (t + 1 < Tt) {
            for (int i = tid; i < 64*128; i += THR) {
                int b2 = i >> 7, kq = i & 127;
                *(float4*)&X[b2*XP1 + 64 + kq*4] =
                    __ldcg((const float4*)&d_hid1[(b2*Tt + t)*512 + kq*4]);
            }
            for (int i = tid; i < 192; i += THR) {
                int b2 = i / 3, kk = i % 3;
                X[b2*XP1 + kk] = strks[(b2*Tt + t + 1)*3 + kk];
            }
        }
        GRID_BAR();   // wbuf(t) visible everywhere

        if (t + 1 < Tt) {
            for (int i = tid; i < 3840; i += THR) {
                int b2 = i / 60, kk = i % 60;
                X[b2*XP1 + 3 + kk] = __ldcg(&d_wbuf[b2*60 + kk]);
            }
        }
        __syncthreads();
    }

    // ================= phase 2 =================
    {
        const float4* src = (const float4*)(d_P2 + bb*17408);
        for (int i = tid; i < 4352; i += THR) ((float4*)W)[i] = src[i];
    }
    const float bs20 = wg ? 0.f : d_b2p[bb*16 + rq*4 + 0];
    const float bs21 = wg ? 0.f : d_b2p[bb*16 + rq*4 + 1];
    const float bs22 = wg ? 0.f : d_b2p[bb*16 + rq*4 + 2];
    const float bs23 = wg ? 0.f : d_b2p[bb*16 + rq*4 + 3];
    __syncthreads();

    for (int t = 0; t < Tt; t++) {
        float a0 = bs20, a1 = bs21, a2 = bs22, a3 = bs23;

        // half A: k 0..543 = hid1(t)[0..511] | strk(3) | win[0..28]
        for (int i = tid; i < 64*128; i += THR) {
            int b2 = i >> 7, kq = i & 127;
            *(float4*)&X[b2*XP2 + kq*4] =
                __ldcg((const float4*)&d_hid1[(b2*Tt + t)*512 + kq*4]);
        }
        for (int i = tid; i < 2048; i += THR) {
            int b2 = i >> 5, kk = i & 31;
            int k = 512 + kk;
            float v = (k < 515) ? strks[(b2*Tt + t)*3 + (k-512)]
                                : __ldcg(&d_win[(b2*Tt + t)*60 + (k-515)]);
            X[b2*XP2 + 512 + kk] = v;
        }
        __syncthreads();
        // K split within half A: wg0 -> 0..271, wg1 -> 272..543
        mac_k(&X[b*XP2 + wg*272], &W[wg*272*16 + rq*4], 272, a0, a1, a2, a3);
        __syncthreads();

        // half B: k 544..1087 = win[29..59] | pad | hid2(t-1)
        for (int i = tid; i < 2048; i += THR) {
            int b2 = i >> 5, kk = i & 31;
            int k = 544 + kk;
            float v = (k < 575) ? __ldcg(&d_win[(b2*Tt + t)*60 + (k-515)]) : 0.f;
            X[b2*XP2 + kk] = v;
        }
        for (int i = tid; i < 64*128; i += THR) {
            int b2 = i >> 7, kq = i & 127;
            float4 v = (t > 0) ? __ldcg((const float4*)&d_hid2[(b2*Tt + t - 1)*512 + kq*4])
                               : make_float4(0.f,0.f,0.f,0.f);
            *(float4*)&X[b2*XP2 + 32 + kq*4] = v;
        }
        __syncthreads();
        mac_k(&X[b*XP2 + wg*272], &W[(544 + wg*272)*16 + rq*4], 272, a0, a1, a2, a3);

        float* g = Gm + wg*1088 + b*17 + rq*4;
        g[0] = a0; g[1] = a1; g[2] = a2; g[3] = a3;
        __syncthreads();
        if (tid < 256) {
            int b2 = tid >> 2, uu = tid & 3;
            int u = bb*4 + uu;
            float ig = Gm[b2*17 +  0 + uu] + Gm[1088 + b2*17 +  0 + uu];
            float fg = Gm[b2*17 +  4 + uu] + Gm[1088 + b2*17 +  4 + uu];
            float gg = Gm[b2*17 +  8 + uu] + Gm[1088 + b2*17 +  8 + uu];
            float og = Gm[b2*17 + 12 + uu] + Gm[1088 + b2*17 + 12 + uu];
            float c = sigf(fg)*d_c2[b2*512 + u] + sigf(ig)*tanhf(gg);
            float h = sigf(og)*tanhf(c);
            d_c2[b2*512 + u] = c;
            d_hid2[(b2*Tt + t)*512 + u] = h;
        }
        GRID_BAR();   // h2(t) visible everywhere
    }
}

// ---------------- MDN head ----------------
__global__ void mdn_kernel(const float* __restrict__ bmdn, float* __restrict__ out)
{
    __shared__ float rows[8*1024];
    __shared__ float pbuf[8*128];
    const int tid  = threadIdx.x;
    const int row0 = blockIdx.x*8;

    for (int idx = tid; idx < 8*1024; idx += 256) {
        int rr = idx >> 10, k2 = idx & 1023;
        int bt = row0 + rr;
        rows[idx] = (k2 < 512) ? d_hid1[bt*512 + k2] : d_hid2[bt*512 + (k2-512)];
    }
    __syncthreads();

    const int o    = tid & 127;
    const int half = tid >> 7;
    if (o < MDNO) {
        float acc[4];
        float bbv = bmdn[o];
        #pragma unroll
        for (int i = 0; i < 4; i++) acc[i] = bbv;
        const float* wr = &d_Weff[o*1024];
        for (int k2 = 0; k2 < 1024; k2 += 4) {
            float4 w = *(const float4*)(wr + k2);
            #pragma unroll
            for (int i = 0; i < 4; i++) {
                const float* x = &rows[(half*4 + i)*1024 + k2];
                acc[i] += w.x*x[0] + w.y*x[1] + w.z*x[2] + w.w*x[3];
            }
        }
        #pragma unroll
        for (int i = 0; i < 4; i++) pbuf[(half*4 + i)*128 + o] = acc[i];
    }
    __syncthreads();

    const int warp = tid >> 5, lane = tid & 31;
    const int bt = row0 + warp;
    const float* p = &pbuf[warp*128];

    float v = (lane < 20) ? p[lane] : -1e30f;
    float mx = v;
    #pragma unroll
    for (int off = 16; off; off >>= 1) mx = fmaxf(mx, __shfl_xor_sync(0xffffffffu, mx, off));
    float e = (lane < 20) ? expf(v - mx) : 0.f;
    float sum = e;
    #pragma unroll
    for (int off = 16; off; off >>= 1) sum += __shfl_xor_sync(0xffffffffu, sum, off);

    if (lane < 20) {
        float* base = out + BT;
        base[            bt*20 + lane] = e / sum;
        base[1*BT*20  +  bt*20 + lane] = p[20 + lane];
        base[2*BT*20  +  bt*20 + lane] = p[40 + lane];
        base[3*BT*20  +  bt*20 + lane] = expf(p[60 + lane]);
        base[4*BT*20  +  bt*20 + lane] = expf(p[80 + lane]);
        base[5*BT*20  +  bt*20 + lane] = tanhf(p[100 + lane]);
    }
    if (lane == 20) out[bt] = 1.f/(1.f + expf(-p[120]));
}

// ---------------- launch (5 graph nodes) ----------------
extern "C" void kernel_launch(void* const* d_in, const int* in_sizes, int n_in,
                              void* d_out, int out_size)
{
    const float* strks   = (const float*)d_in[0];
    const float* sents_m = (const float*)d_in[3];
    const float* onehots = (const float*)d_in[4];
    const float* w_prev  = (const float*)d_in[5];
    const float* Wih1    = (const float*)d_in[6];
    const float* Whh1    = (const float*)d_in[7];
    const float* bih1    = (const float*)d_in[8];
    const float* bhh1    = (const float*)d_in[9];
    const float* Wih2    = (const float*)d_in[10];
    const float* Whh2    = (const float*)d_in[11];
    const float* bih2    = (const float*)d_in[12];
    const float* bhh2    = (const float*)d_in[13];
    const float* Wsw     = (const float*)d_in[14];
    const float* bsw     = (const float*)d_in[15];
    const float* Wmdn    = (const float*)d_in[16];
    const float* bmdn    = (const float*)d_in[17];
    float* out = (float*)d_out;

    static int smem_set = 0;
    if (!smem_set) {
        cudaFuncSetAttribute(main_scan, cudaFuncAttributeMaxDynamicSharedMemorySize,
                             SM_TOT*sizeof(float));
        smem_set = 1;
    }

    prep_pack1<<<(NBLK*576*16  + 255)/256, 256>>>(Wih1, Whh1);
    prep_pack2<<<(NBLK*1088*16 + 255)/256, 256>>>(Wih2, Whh2);
    prep_misc <<<(MDNO*1024 + 255)/256, 256>>>(bih1, bhh1, bih2, bhh2, Wmdn, w_prev);

    main_scan<<<NBLK, THR, SM_TOT*sizeof(float)>>>(strks, sents_m, onehots, Wsw, bsw);
    mdn_kernel<<<BT/8, 256>>>(bmdn, out);
}

// round 9
// speedup vs baseline: 2.6464x; 1.2401x over previous
#include <cuda_runtime.h>
#include <math.h>

// ---------------- problem constants ----------------
#define Bz   64
#define Tt   800
#define Hh   512
#define Kk   10
#define SENT 60
#define G4   2048            // 4*H
#define BT   (Bz*Tt)         // 51200
#define MDNO 121             // 1 + 6*M
#define NBLK 128             // persistent grid (<=148 SMs -> co-resident)
#define THR  512             // 16 warps

// weight smem layout: [ks][k][16 rows], ks-stride padded so consecutive ks differ
// by 16 banks (stride % 32 == 16) -> conflict-free LDS.128 within each 8-lane phase.
#define W1KS 1168            // 72*16 + 16
#define W1SZ (8*W1KS)        // 9344 floats per block
#define W2KS 1104            // 68*16 + 16
#define W2HALF (8*W2KS)      // 8832
#define W2SZ (2*W2HALF)      // 17664 floats per block

// dynamic smem layout (floats)
#define XP1  580             // phase1 x pitch (576 cols) ; %32==4
#define XP2  548             // phase2 x pitch (544 cols/half) ; %32==4
#define SM_W 0               // 17664 floats (phase2); phase1 uses first 9344
#define SM_X 17664           // 37120 floats (64*580)
#define SM_G (17664+37120)   // 54784: gate staging 64*17 = 1088
#define SM_A (SM_G+1088)     // 55872: attention scratch (640)
#define SM_TOT (SM_A+640)    // 56512 floats = 226048 bytes (< 227KB opt-in)

// ---------------- persistent device scratch (no allocations) ----------------
__device__ float d_hid1[BT*Hh];
__device__ float d_hid2[BT*Hh];
__device__ float d_win [BT*SENT];
__device__ float d_c1  [Bz*Hh];
__device__ float d_c2  [Bz*Hh];
__device__ float d_kbuf[Bz*Kk];
__device__ float d_wbuf[Bz*SENT];

__device__ float d_P1 [NBLK*W1SZ];
__device__ float d_P2 [NBLK*W2SZ];
__device__ float d_b1p[G4];
__device__ float d_b2p[G4];
__device__ float d_Weff[MDNO*1024];

__device__ unsigned          d_bar_count;
__device__ volatile unsigned d_bar_sense;

__device__ __forceinline__ float sigf(float x) { return 1.f/(1.f+expf(-x)); }

// ---------------- prep kernels ----------------
// phase1 weights: k_global = ks*72 + k, 0..575 = [strk3|win60|pad][rec 512]
__global__ void prep_pack1(const float* __restrict__ Wih1, const float* __restrict__ Whh1) {
    int idx = blockIdx.x*blockDim.x + threadIdx.x;
    if (idx >= NBLK*W1SZ) return;
    int bb = idx / W1SZ, rem = idx % W1SZ;
    int ks = rem / W1KS, r2 = rem % W1KS;
    int k = r2 >> 4, rr = r2 & 15;
    float v = 0.f;
    if (k < 72) {
        int gate = rr >> 2, uu = rr & 3;
        int grow = gate*512 + bb*4 + uu;
        int kg = ks*72 + k;
        if (kg < 64) v = (kg < 63) ? Wih1[grow*63 + kg] : 0.f;
        else         v = Whh1[grow*512 + (kg-64)];
    }
    d_P1[idx] = v;
}

// phase2 weights: k_global = half*544 + ks*68 + k, 0..1087
__global__ void prep_pack2(const float* __restrict__ Wih2, const float* __restrict__ Whh2) {
    int idx = blockIdx.x*blockDim.x + threadIdx.x;
    if (idx >= NBLK*W2SZ) return;
    int bb = idx / W2SZ, rem = idx % W2SZ;
    int half = rem / W2HALF, r3 = rem % W2HALF;
    int ks = r3 / W2KS, r2 = r3 % W2KS;
    int k = r2 >> 4, rr = r2 & 15;
    float v = 0.f;
    if (k < 68) {
        int gate = rr >> 2, uu = rr & 3;
        int grow = gate*512 + bb*4 + uu;
        int kg = half*544 + ks*68 + k;
        if      (kg < 512)  v = Wih2[grow*575 + 3 + kg];
        else if (kg < 515)  v = Wih2[grow*575 + (kg-512)];
        else if (kg < 575)  v = Wih2[grow*575 + kg];
        else if (kg == 575) v = 0.f;
        else                v = Whh2[grow*512 + (kg-576)];
    }
    d_P2[idx] = v;
}

__global__ void prep_misc(const float* __restrict__ bih1, const float* __restrict__ bhh1,
                          const float* __restrict__ bih2, const float* __restrict__ bhh2,
                          const float* __restrict__ Wmdn, const float* __restrict__ w_prev) {
    int idx = blockIdx.x*blockDim.x + threadIdx.x;
    if (idx < MDNO*1024) {
        int o = idx >> 10, k = idx & 1023;
        float v = Wmdn[o*1536 + k];
        if (k >= 512) v += Wmdn[o*1536 + k + 512];
        d_Weff[idx] = v;
    }
    if (idx < G4) {
        int bb = idx >> 4, rr = idx & 15;
        int gate = rr >> 2, uu = rr & 3;
        int grow = gate*512 + bb*4 + uu;
        d_b1p[idx] = bih1[grow] + bhh1[grow];
        d_b2p[idx] = bih2[grow] + bhh2[grow];
    }
    if (idx < Bz*Hh) { d_c1[idx] = 0.f; d_c2[idx] = 0.f; }
    if (idx < Bz*Kk)   d_kbuf[idx] = 0.f;
    if (idx < Bz*SENT) d_wbuf[idx] = w_prev[idx];
    if (idx == 0) { d_bar_count = 0u; d_bar_sense = 0u; }
}

// ---------------- grid barrier (sense reversal) ----------------
#define GRID_BAR()                                                        \
    do {                                                                  \
        __threadfence();                                                  \
        __syncthreads();                                                  \
        if (tid == 0) {                                                   \
            unsigned s = s_sense ^ 1u; s_sense = s;                       \
            if (atomicAdd(&d_bar_count, 1u) == NBLK - 1u) {               \
                d_bar_count = 0u;                                         \
                __threadfence();                                          \
                d_bar_sense = s;                                          \
            } else {                                                      \
                while (d_bar_sense != s) { __nanosleep(32); }             \
            }                                                             \
        }                                                                 \
        __syncthreads();                                                  \
    } while (0)

// ---------------- MAC: 4 rows x 4 batch-cols over a k-range ----------------
// xr = X + b0*xp + kbase ; wr = W + ks_base + rq*4 (layout [k][16])
__device__ __forceinline__ void mac_ks(const float* __restrict__ xr, int xp,
                                       const float* __restrict__ wr, int cnt,
                                       float (&acc)[4][4])
{
    #pragma unroll 2
    for (int k = 0; k < cnt; k += 4) {
        float4 w0 = *(const float4*)(wr + (k+0)*16);
        float4 w1 = *(const float4*)(wr + (k+1)*16);
        float4 w2 = *(const float4*)(wr + (k+2)*16);
        float4 w3 = *(const float4*)(wr + (k+3)*16);
        #pragma unroll
        for (int j = 0; j < 4; j++) {
            float4 xv = *(const float4*)(xr + j*xp + k);
            acc[j][0] = fmaf(w0.x, xv.x, fmaf(w1.x, xv.y, fmaf(w2.x, xv.z, fmaf(w3.x, xv.w, acc[j][0]))));
            acc[j][1] = fmaf(w0.y, xv.x, fmaf(w1.y, xv.y, fmaf(w2.y, xv.z, fmaf(w3.y, xv.w, acc[j][1]))));
            acc[j][2] = fmaf(w0.z, xv.x, fmaf(w1.z, xv.y, fmaf(w2.z, xv.z, fmaf(w3.z, xv.w, acc[j][2]))));
            acc[j][3] = fmaf(w0.w, xv.x, fmaf(w1.w, xv.y, fmaf(w2.w, xv.z, fmaf(w3.w, xv.w, acc[j][3]))));
        }
    }
}

// butterfly-reduce acc across the 8 ks lanes (bits 2..4 of lane id)
#define KS_REDUCE(acc)                                                        \
    do {                                                                      \
        _Pragma("unroll")                                                     \
        for (int off = 4; off <= 16; off <<= 1) {                             \
            _Pragma("unroll")                                                 \
            for (int j = 0; j < 4; j++) {                                     \
                _Pragma("unroll")                                             \
                for (int i = 0; i < 4; i++)                                   \
                    acc[j][i] += __shfl_xor_sync(0xffffffffu, acc[j][i], off);\
            }                                                                 \
        }                                                                     \
    } while (0)

// ---------------- persistent main kernel ----------------
extern __shared__ float sm[];

__global__ void __launch_bounds__(THR, 1)
main_scan(const float* __restrict__ strks,
          const float* __restrict__ sents_m,
          const float* __restrict__ onehots,
          const float* __restrict__ Wsw,
          const float* __restrict__ bsw)
{
    __shared__ unsigned s_sense;
    float* W  = sm + SM_W;
    float* X  = sm + SM_X;
    float* Gm = sm + SM_G;     // [64][17] gates
    float* At = sm + SM_A;     // shh 512 | pa@512 | pb@524 | pk@536 | phi@552

    const int tid = threadIdx.x;
    const int bb  = blockIdx.x;
    if (tid == 0) s_sense = 0u;

    const int warp = tid >> 5;       // 0..15 -> batch quad
    const int lane = tid & 31;
    const int ks   = lane >> 2;      // 0..7: K slice
    const int rq   = lane & 3;       // 0..3: gate -> rows rq*4..+3
    const int b0   = warp*4;         // 4 batch columns

    // cell-update thread's biases (tid < 256: b2 = tid>>2, uu = tid&3)
    float bi1[4], bi2[4];
    {
        int uu = tid & 3;
        #pragma unroll
        for (int g = 0; g < 4; g++) {
            bi1[g] = d_b1p[bb*16 + g*4 + uu];
            bi2[g] = d_b2p[bb*16 + g*4 + uu];
        }
    }

    // ================= phase 1 =================
    {
        const float4* src = (const float4*)(d_P1 + bb*W1SZ);
        for (int i = tid; i < W1SZ/4; i += THR) ((float4*)W)[i] = src[i];
    }
    // pre-fill X for t=0
    for (int i = tid; i < 4096; i += THR) {
        int b2 = i >> 6, kk = i & 63;
        float v = 0.f;
        if (kk < 3)       v = strks[(b2*Tt + 0)*3 + kk];
        else if (kk < 63) v = __ldcg(&d_wbuf[b2*60 + kk - 3]);
        X[b2*XP1 + kk] = v;
    }
    for (int i = tid; i < 64*128; i += THR) {
        int b2 = i >> 7, kq = i & 127;
        *(float4*)&X[b2*XP1 + 64 + kq*4] = make_float4(0.f,0.f,0.f,0.f);
    }
    __syncthreads();

    for (int t = 0; t < Tt; t++) {
        float acc[4][4];
        #pragma unroll
        for (int j = 0; j < 4; j++)
            #pragma unroll
            for (int i = 0; i < 4; i++) acc[j][i] = 0.f;

        mac_ks(&X[b0*XP1 + ks*72], XP1, &W[ks*W1KS + rq*4], 72, acc);
        KS_REDUCE(acc);
        if (lane < 4) {
            #pragma unroll
            for (int j = 0; j < 4; j++)
                #pragma unroll
                for (int i = 0; i < 4; i++)
                    Gm[(b0+j)*17 + lane*4 + i] = acc[j][i];
        }
        __syncthreads();
        if (tid < 256) {
            int b2 = tid >> 2, uu = tid & 3;
            int u = bb*4 + uu;
            float ig = Gm[b2*17 +  0 + uu] + bi1[0];
            float fg = Gm[b2*17 +  4 + uu] + bi1[1];
            float gg = Gm[b2*17 +  8 + uu] + bi1[2];
            float og = Gm[b2*17 + 12 + uu] + bi1[3];
            float c = sigf(fg)*d_c1[b2*512 + u] + sigf(ig)*tanhf(gg);
            float h = sigf(og)*tanhf(c);
            d_c1[b2*512 + u] = c;
            d_hid1[(b2*Tt + t)*512 + u] = h;
        }
        GRID_BAR();   // h1(t) visible everywhere

        // attention: blocks 0..63 handle batch bb (overlaps other blocks' fills)
        if (bb < 64) {
            float* shh = At; float* pa = At+512; float* pb = At+524;
            float* pk = At+536; float* phi = At+552;
            for (int i = tid; i < 512; i += THR) shh[i] = __ldcg(&d_hid1[(bb*Tt + t)*512 + i]);
            __syncthreads();
            for (int o = warp; o < 30; o += 16) {
                const float* wr = &Wsw[o*512];
                float s = 0.f;
                #pragma unroll 4
                for (int k2 = lane; k2 < 512; k2 += 32) s += wr[k2]*shh[k2];
                #pragma unroll
                for (int off = 16; off; off >>= 1) s += __shfl_down_sync(0xffffffffu, s, off);
                if (lane == 0) {
                    s += bsw[o];
                    if (o < 10)      pa[o] = expf(s);
                    else if (o < 20) pb[o-10] = expf(s);
                    else {
                        float kn = d_kbuf[bb*10 + (o-20)] + expf(s);
                        pk[o-20] = kn;
                        d_kbuf[bb*10 + (o-20)] = kn;
                    }
                }
            }
            __syncthreads();
            if (tid < 64) {
                float uu = (float)tid, s = 0.f;
                #pragma unroll
                for (int j = 0; j < 10; j++) {
                    float d = pk[j] - uu;
                    s += pa[j]*expf(-pb[j]*d*d);
                }
                phi[tid] = s * sents_m[bb*64 + tid];
            }
            __syncthreads();
            if (tid < 60) {
                float s = 0.f;
                const float* oh = &onehots[bb*64*60 + tid];
                for (int u2 = 0; u2 < 64; u2++) s += phi[u2]*oh[u2*60];
                d_wbuf[bb*60 + tid] = s;
                d_win[(bb*Tt + t)*60 + tid] = s;
            }
        }

        if (t + 1 < Tt) {
            for (int i = tid; i < 64*128; i += THR) {
                int b2 = i >> 7, kq = i & 127;
                *(float4*)&X[b2*XP1 + 64 + kq*4] =
                    __ldcg((const float4*)&d_hid1[(b2*Tt + t)*512 + kq*4]);
            }
            for (int i = tid; i < 192; i += THR) {
                int b2 = i / 3, kk = i % 3;
                X[b2*XP1 + kk] = strks[(b2*Tt + t + 1)*3 + kk];
            }
        }
        GRID_BAR();   // wbuf(t) visible everywhere

        if (t + 1 < Tt) {
            for (int i = tid; i < 3840; i += THR) {
                int b2 = i / 60, kk = i % 60;
                X[b2*XP1 + 3 + kk] = __ldcg(&d_wbuf[b2*60 + kk]);
            }
        }
        __syncthreads();
    }

    // ================= phase 2 =================
    {
        const float4* src = (const float4*)(d_P2 + bb*W2SZ);
        for (int i = tid; i < W2SZ/4; i += THR) ((float4*)W)[i] = src[i];
    }
    __syncthreads();

    for (int t = 0; t < Tt; t++) {
        float acc[4][4];
        #pragma unroll
        for (int j = 0; j < 4; j++)
            #pragma unroll
            for (int i = 0; i < 4; i++) acc[j][i] = 0.f;

        // half A: k 0..543 = hid1(t)[0..511] | strk(3) | win[0..28]
        for (int i = tid; i < 64*128; i += THR) {
            int b2 = i >> 7, kq = i & 127;
            *(float4*)&X[b2*XP2 + kq*4] =
                __ldcg((const float4*)&d_hid1[(b2*Tt + t)*512 + kq*4]);
        }
        for (int i = tid; i < 2048; i += THR) {
            int b2 = i >> 5, kk = i & 31;
            int k = 512 + kk;
            float v = (k < 515) ? strks[(b2*Tt + t)*3 + (k-512)]
                                : __ldcg(&d_win[(b2*Tt + t)*60 + (k-515)]);
            X[b2*XP2 + 512 + kk] = v;
        }
        __syncthreads();
        mac_ks(&X[b0*XP2 + ks*68], XP2, &W[ks*W2KS + rq*4], 68, acc);
        __syncthreads();

        // half B: k 544..1087 = win[29..59] | pad | hid2(t-1)
        for (int i = tid; i < 2048; i += THR) {
            int b2 = i >> 5, kk = i & 31;
            int k = 544 + kk;
            float v = (k < 575) ? __ldcg(&d_win[(b2*Tt + t)*60 + (k-515)]) : 0.f;
            X[b2*XP2 + kk] = v;
        }
        for (int i = tid; i < 64*128; i += THR) {
            int b2 = i >> 7, kq = i & 127;
            float4 v = (t > 0) ? __ldcg((const float4*)&d_hid2[(b2*Tt + t - 1)*512 + kq*4])
                               : make_float4(0.f,0.f,0.f,0.f);
            *(float4*)&X[b2*XP2 + 32 + kq*4] = v;
        }
        __syncthreads();
        mac_ks(&X[b0*XP2 + ks*68], XP2, &W[W2HALF + ks*W2KS + rq*4], 68, acc);

        KS_REDUCE(acc);
        if (lane < 4) {
            #pragma unroll
            for (int j = 0; j < 4; j++)
                #pragma unroll
                for (int i = 0; i < 4; i++)
                    Gm[(b0+j)*17 + lane*4 + i] = acc[j][i];
        }
        __syncthreads();
        if (tid < 256) {
            int b2 = tid >> 2, uu = tid & 3;
            int u = bb*4 + uu;
            float ig = Gm[b2*17 +  0 + uu] + bi2[0];
            float fg = Gm[b2*17 +  4 + uu] + bi2[1];
            float gg = Gm[b2*17 +  8 + uu] + bi2[2];
            float og = Gm[b2*17 + 12 + uu] + bi2[3];
            float c = sigf(fg)*d_c2[b2*512 + u] + sigf(ig)*tanhf(gg);
            float h = sigf(og)*tanhf(c);
            d_c2[b2*512 + u] = c;
            d_hid2[(b2*Tt + t)*512 + u] = h;
        }
        GRID_BAR();   // h2(t) visible everywhere
    }
}

// ---------------- MDN head ----------------
__global__ void mdn_kernel(const float* __restrict__ bmdn, float* __restrict__ out)
{
    __shared__ float rows[8*1024];
    __shared__ float pbuf[8*128];
    const int tid  = threadIdx.x;
    const int row0 = blockIdx.x*8;

    for (int idx = tid; idx < 8*1024; idx += 256) {
        int rr = idx >> 10, k2 = idx & 1023;
        int bt = row0 + rr;
        rows[idx] = (k2 < 512) ? d_hid1[bt*512 + k2] : d_hid2[bt*512 + (k2-512)];
    }
    __syncthreads();

    const int o    = tid & 127;
    const int half = tid >> 7;
    if (o < MDNO) {
        float acc[4];
        float bbv = bmdn[o];
        #pragma unroll
        for (int i = 0; i < 4; i++) acc[i] = bbv;
        const float* wr = &d_Weff[o*1024];
        for (int k2 = 0; k2 < 1024; k2 += 4) {
            float4 w = *(const float4*)(wr + k2);
            #pragma unroll
            for (int i = 0; i < 4; i++) {
                const float* x = &rows[(half*4 + i)*1024 + k2];
                acc[i] += w.x*x[0] + w.y*x[1] + w.z*x[2] + w.w*x[3];
            }
        }
        #pragma unroll
        for (int i = 0; i < 4; i++) pbuf[(half*4 + i)*128 + o] = acc[i];
    }
    __syncthreads();

    const int warp = tid >> 5, lane = tid & 31;
    const int bt = row0 + warp;
    const float* p = &pbuf[warp*128];

    float v = (lane < 20) ? p[lane] : -1e30f;
    float mx = v;
    #pragma unroll
    for (int off = 16; off; off >>= 1) mx = fmaxf(mx, __shfl_xor_sync(0xffffffffu, mx, off));
    float e = (lane < 20) ? expf(v - mx) : 0.f;
    float sum = e;
    #pragma unroll
    for (int off = 16; off; off >>= 1) sum += __shfl_xor_sync(0xffffffffu, sum, off);

    if (lane < 20) {
        float* base = out + BT;
        base[            bt*20 + lane] = e / sum;
        base[1*BT*20  +  bt*20 + lane] = p[20 + lane];
        base[2*BT*20  +  bt*20 + lane] = p[40 + lane];
        base[3*BT*20  +  bt*20 + lane] = expf(p[60 + lane]);
        base[4*BT*20  +  bt*20 + lane] = expf(p[80 + lane]);
        base[5*BT*20  +  bt*20 + lane] = tanhf(p[100 + lane]);
    }
    if (lane == 20) out[bt] = 1.f/(1.f + expf(-p[120]));
}

// ---------------- launch (5 graph nodes) ----------------
extern "C" void kernel_launch(void* const* d_in, const int* in_sizes, int n_in,
                              void* d_out, int out_size)
{
    const float* strks   = (const float*)d_in[0];
    const float* sents_m = (const float*)d_in[3];
    const float* onehots = (const float*)d_in[4];
    const float* w_prev  = (const float*)d_in[5];
    const float* Wih1    = (const float*)d_in[6];
    const float* Whh1    = (const float*)d_in[7];
    const float* bih1    = (const float*)d_in[8];
    const float* bhh1    = (const float*)d_in[9];
    const float* Wih2    = (const float*)d_in[10];
    const float* Whh2    = (const float*)d_in[11];
    const float* bih2    = (const float*)d_in[12];
    const float* bhh2    = (const float*)d_in[13];
    const float* Wsw     = (const float*)d_in[14];
    const float* bsw     = (const float*)d_in[15];
    const float* Wmdn    = (const float*)d_in[16];
    const float* bmdn    = (const float*)d_in[17];
    float* out = (float*)d_out;

    static int smem_set = 0;
    if (!smem_set) {
        cudaFuncSetAttribute(main_scan, cudaFuncAttributeMaxDynamicSharedMemorySize,
                             SM_TOT*sizeof(float));
        smem_set = 1;
    }

    prep_pack1<<<(NBLK*W1SZ + 255)/256, 256>>>(Wih1, Whh1);
    prep_pack2<<<(NBLK*W2SZ + 255)/256, 256>>>(Wih2, Whh2);
    prep_misc <<<(MDNO*1024 + 255)/256, 256>>>(bih1, bhh1, bih2, bhh2, Wmdn, w_prev);

    main_scan<<<NBLK, THR, SM_TOT*sizeof(float)>>>(strks, sents_m, onehots, Wsw, bsw);
    mdn_kernel<<<BT/8, 256>>>(bmdn, out);
}

// round 10
// speedup vs baseline: 2.8487x; 1.0764x over previous
#include <cuda_runtime.h>
#include <math.h>

// ---------------- problem constants ----------------
#define Bz   64
#define Tt   800
#define Hh   512
#define SENT 60
#define G4   2048
#define BT   (Bz*Tt)
#define MDNO 121
#define NBLK 128
#define THR  512

// X layout: per batch row, 16 slices x 36 words (pitch 580; 580%32==4)
//   phase1 slice: j0..31 = h1-rec, j32..35 = misc (strk3+win60+pad over slices)
//   phase2 slice: j0..31 = h1 (MAC-A) then overwritten by h2 (MAC-B); j32..35 = misc
#define XP   580
#define SLC  36
// weight layouts [ks][j][16 rows], slice strides %32==16 (conflict-free pairs)
#define P1KS 592             // 37*16
#define P1SZ (16*P1KS)       // 9472
#define P2KS 1104            // 69*16
#define P2SZ (16*P2KS)       // 17664

#define SM_W 0
#define SM_X 17664           // 64*580 = 37120
#define SM_G (17664+37120)   // Gm: 2 x 64*20 = 2560 (attention scratch aliases this)
#define SM_TOT (SM_G+2560)   // 57344 floats = 229376 bytes

// ---------------- persistent device scratch ----------------
__device__ float d_hid1[BT*Hh];
__device__ float d_hid2[BT*Hh];
__device__ float d_win [BT*SENT];
__device__ float d_c1  [Bz*Hh];
__device__ float d_c2  [Bz*Hh];
__device__ float d_kbuf[Bz*10];
__device__ float d_wbuf[Bz*SENT];

__device__ float d_P1 [NBLK*P1SZ];
__device__ float d_P2 [NBLK*P2SZ];
__device__ float d_b1p[G4];
__device__ float d_b2p[G4];
__device__ float d_Weff[MDNO*1024];

__device__ unsigned          d_cnt[2];
__device__ volatile unsigned d_epoch;

__device__ __forceinline__ float sigf(float x) { return 1.f/(1.f+expf(-x)); }

// ---------------- prep kernels ----------------
__global__ void prep_pack1(const float* __restrict__ Wih1, const float* __restrict__ Whh1) {
    int idx = blockIdx.x*blockDim.x + threadIdx.x;
    if (idx >= NBLK*P1SZ) return;
    int bb = idx / P1SZ, rem = idx % P1SZ;
    int ks = rem / P1KS, r2 = rem % P1KS;
    int j = r2 >> 4, rr = r2 & 15;
    int gate = rr >> 2, uu = rr & 3;
    int grow = gate*512 + bb*4 + uu;
    float v = 0.f;
    if (j < 32)      v = Whh1[grow*512 + ks*32 + j];          // recurrent
    else if (j < 36) { int e = ks*4 + (j-32);                  // misc [strk3|win60|pad]
                       if (e < 63) v = Wih1[grow*63 + e]; }
    d_P1[idx] = v;
}

__global__ void prep_pack2(const float* __restrict__ Wih2, const float* __restrict__ Whh2) {
    int idx = blockIdx.x*blockDim.x + threadIdx.x;
    if (idx >= NBLK*P2SZ) return;
    int bb = idx / P2SZ, rem = idx % P2SZ;
    int ks = rem / P2KS, r2 = rem % P2KS;
    int j = r2 >> 4, rr = r2 & 15;
    int gate = rr >> 2, uu = rr & 3;
    int grow = gate*512 + bb*4 + uu;
    float v = 0.f;
    if (j < 32)      v = Wih2[grow*575 + 3 + ks*32 + j];       // h1 (MAC-A)
    else if (j < 36) { int e = ks*4 + (j-32);                   // misc
                       if (e < 3)       v = Wih2[grow*575 + e];
                       else if (e < 63) v = Wih2[grow*575 + 515 + (e-3)]; }
    else if (j < 68) v = Whh2[grow*512 + ks*32 + (j-36)];      // h2 (MAC-B)
    d_P2[idx] = v;
}

__global__ void prep_misc(const float* __restrict__ bih1, const float* __restrict__ bhh1,
                          const float* __restrict__ bih2, const float* __restrict__ bhh2,
                          const float* __restrict__ Wmdn, const float* __restrict__ w_prev) {
    int idx = blockIdx.x*blockDim.x + threadIdx.x;
    if (idx < MDNO*1024) {
        int o = idx >> 10, k = idx & 1023;
        float v = Wmdn[o*1536 + k];
        if (k >= 512) v += Wmdn[o*1536 + k + 512];
        d_Weff[idx] = v;
    }
    if (idx < G4) {
        int bb = idx >> 4, rr = idx & 15;
        int gate = rr >> 2, uu = rr & 3;
        int grow = gate*512 + bb*4 + uu;
        d_b1p[idx] = bih1[grow] + bhh1[grow];
        d_b2p[idx] = bih2[grow] + bhh2[grow];
    }
    if (idx < Bz*Hh) { d_c1[idx] = 0.f; d_c2[idx] = 0.f; }
    if (idx < Bz*10)   d_kbuf[idx] = 0.f;
    if (idx < Bz*SENT) d_wbuf[idx] = w_prev[idx];
    if (idx == 0) { d_cnt[0] = 0u; d_cnt[1] = 0u; d_epoch = 0u; }
}

// ---------------- split grid barrier (epoch + dual counters) ----------------
#define BAR_ARRIVE()                                                          \
    do {                                                                      \
        bseq++;                                                               \
        __syncthreads();                                                      \
        if (tid == 0) {                                                       \
            __threadfence();                                                  \
            if (atomicAdd(&d_cnt[bseq & 1u], 1u) == NBLK - 1u) {              \
                d_cnt[bseq & 1u] = 0u;                                        \
                __threadfence();                                              \
                d_epoch = bseq;                                               \
            }                                                                 \
        }                                                                     \
    } while (0)

#define BAR_WAIT()                                                            \
    do {                                                                      \
        if (tid == 0) {                                                       \
            while ((int)(d_epoch - bseq) < 0) __nanosleep(32);                \
        }                                                                     \
        __syncthreads();                                                      \
    } while (0)

// ---------------- MAC: 4 rows x 8 batch-cols over chunks of 4 k ----------------
__device__ __forceinline__ void mac_run(const float* __restrict__ xr,
                                        const float* __restrict__ wr,
                                        int chunks, float (&acc)[8][4])
{
    #pragma unroll 2
    for (int c = 0; c < chunks; c++) {
        int k = c*4;
        float4 w0 = *(const float4*)(wr + (k+0)*16);
        float4 w1 = *(const float4*)(wr + (k+1)*16);
        float4 w2 = *(const float4*)(wr + (k+2)*16);
        float4 w3 = *(const float4*)(wr + (k+3)*16);
        #pragma unroll
        for (int j = 0; j < 8; j++) {
            float4 xv = *(const float4*)(xr + j*XP + k);
            acc[j][0] = fmaf(w0.x, xv.x, fmaf(w1.x, xv.y, fmaf(w2.x, xv.z, fmaf(w3.x, xv.w, acc[j][0]))));
            acc[j][1] = fmaf(w0.y, xv.x, fmaf(w1.y, xv.y, fmaf(w2.y, xv.z, fmaf(w3.y, xv.w, acc[j][1]))));
            acc[j][2] = fmaf(w0.z, xv.x, fmaf(w1.z, xv.y, fmaf(w2.z, xv.z, fmaf(w3.z, xv.w, acc[j][2]))));
            acc[j][3] = fmaf(w0.w, xv.x, fmaf(w1.w, xv.y, fmaf(w2.w, xv.z, fmaf(w3.w, xv.w, acc[j][3]))));
        }
    }
}

#define ZERO_ACC(acc)                                                         \
    do { _Pragma("unroll") for (int j = 0; j < 8; j++)                        \
         { _Pragma("unroll") for (int i = 0; i < 4; i++) acc[j][i] = 0.f; } } while (0)

#define KS_REDUCE(acc)                                                        \
    do {                                                                      \
        _Pragma("unroll")                                                     \
        for (int off = 4; off <= 16; off <<= 1) {                             \
            _Pragma("unroll")                                                 \
            for (int j = 0; j < 8; j++) {                                     \
                _Pragma("unroll")                                             \
                for (int i = 0; i < 4; i++)                                   \
                    acc[j][i] += __shfl_xor_sync(0xffffffffu, acc[j][i], off);\
            }                                                                 \
        }                                                                     \
    } while (0)

// ---------------- persistent main kernel ----------------
extern __shared__ float sm[];

__global__ void __launch_bounds__(THR, 1)
main_scan(const float* __restrict__ strks,
          const float* __restrict__ sents_m,
          const float* __restrict__ onehots,
          const float* __restrict__ Wsw,
          const float* __restrict__ bsw)
{
    float* W  = sm + SM_W;
    float* Xs = sm + SM_X;
    float* Gm = sm + SM_G;          // [2][64*20]
    float* At = Gm;                 // attention scratch aliases Gm

    const int tid  = threadIdx.x;
    const int bb   = blockIdx.x;
    const int warp = tid >> 5, lane = tid & 31;
    const int oct  = warp >> 1, kh = warp & 1;
    const int ksl  = lane >> 2, rq = lane & 3;
    const int ks   = kh*8 + ksl;
    const int b0   = oct*8;
    unsigned bseq = 0;

    float bi1[4], bi2[4];
    {
        int uu = tid & 3;
        #pragma unroll
        for (int g = 0; g < 4; g++) {
            bi1[g] = d_b1p[bb*16 + g*4 + uu];
            bi2[g] = d_b2p[bb*16 + g*4 + uu];
        }
    }

    const float* xr = Xs + b0*XP + ks*SLC;
    float acc[8][4];

    // ================= phase 1 =================
    {
        const float4* src = (const float4*)(d_P1 + bb*P1SZ);
        for (int i = tid; i < P1SZ/4; i += THR) ((float4*)W)[i] = src[i];
    }
    // t=0 misc fill: [strk(0) | w_prev | pad]
    for (int i = tid; i < 4096; i += THR) {
        int b2 = i >> 6, e = i & 63;
        float v = 0.f;
        if (e < 3)       v = strks[(b2*Tt + 0)*3 + e];
        else if (e < 63) v = __ldcg(&d_wbuf[b2*60 + e - 3]);
        Xs[b2*XP + (e>>2)*SLC + 32 + (e&3)] = v;
    }
    __syncthreads();

    const float* wr1 = W + ks*P1KS + rq*4;
    ZERO_ACC(acc);  // h1(-1) = 0 -> rec part contributes nothing at t=0

    for (int t = 0; t < Tt; t++) {
        // finish gates: misc chunk (j32..35)
        mac_run(xr + 32, wr1 + 32*16, 1, acc);
        KS_REDUCE(acc);
        if (lane < 4) {
            #pragma unroll
            for (int j = 0; j < 8; j++)
                *(float4*)&Gm[kh*1280 + (b0+j)*20 + rq*4] =
                    make_float4(acc[j][0], acc[j][1], acc[j][2], acc[j][3]);
        }
        __syncthreads();
        if (tid < 256) {
            int b2 = tid >> 2, uu = tid & 3;
            int u = bb*4 + uu;
            float ig = Gm[b2*20 +  0 + uu] + Gm[1280 + b2*20 +  0 + uu] + bi1[0];
            float fg = Gm[b2*20 +  4 + uu] + Gm[1280 + b2*20 +  4 + uu] + bi1[1];
            float gg = Gm[b2*20 +  8 + uu] + Gm[1280 + b2*20 +  8 + uu] + bi1[2];
            float og = Gm[b2*20 + 12 + uu] + Gm[1280 + b2*20 + 12 + uu] + bi1[3];
            float c = sigf(fg)*d_c1[b2*512 + u] + sigf(ig)*tanhf(gg);
            float h = sigf(og)*tanhf(c);
            d_c1[b2*512 + u] = c;
            d_hid1[(b2*Tt + t)*512 + u] = h;
        }
        BAR_ARRIVE();           // bar1: h1(t) ready
        BAR_WAIT();

        if (bb < 64) {          // attention for batch bb
            float* shh = At; float* pa = At+512; float* pb = At+524;
            float* pk = At+536; float* phi = At+552;
            shh[tid] = __ldcg(&d_hid1[(bb*Tt + t)*512 + tid]);
            __syncthreads();
            for (int o = warp; o < 30; o += 16) {
                const float* wrow = &Wsw[o*512];
                float s = 0.f;
                #pragma unroll 4
                for (int k2 = lane; k2 < 512; k2 += 32) s += wrow[k2]*shh[k2];
                #pragma unroll
                for (int off = 16; off; off >>= 1) s += __shfl_down_sync(0xffffffffu, s, off);
                if (lane == 0) {
                    s += bsw[o];
                    if (o < 10)      pa[o] = expf(s);
                    else if (o < 20) pb[o-10] = expf(s);
                    else {
                        float kn = d_kbuf[bb*10 + (o-20)] + expf(s);
                        pk[o-20] = kn;
                        d_kbuf[bb*10 + (o-20)] = kn;
                    }
                }
            }
            __syncthreads();
            if (tid < 64) {
                float uu = (float)tid, s = 0.f;
                #pragma unroll
                for (int j = 0; j < 10; j++) {
                    float d = pk[j] - uu;
                    s += pa[j]*expf(-pb[j]*d*d);
                }
                phi[tid] = s * sents_m[bb*64 + tid];
            }
            __syncthreads();
            if (tid < 60) {
                float s = 0.f;
                const float* oh = &onehots[bb*64*60 + tid];
                for (int u2 = 0; u2 < 64; u2++) s += phi[u2]*oh[u2*60];
                d_wbuf[bb*60 + tid] = s;
                d_win[(bb*Tt + t)*60 + tid] = s;
            }
        }
        BAR_ARRIVE();           // bar2: w(t) ready (arrive early; overlap below)

        ZERO_ACC(acc);
        if (t + 1 < Tt) {
            // rec fill h1(t) -> j0..31 slices, then rec MAC (overlaps bar2 wait)
            for (int i = tid; i < 8192; i += THR) {
                int b2 = i >> 7, kq = i & 127;
                *(float4*)&Xs[b2*XP + (kq>>3)*SLC + (kq&7)*4] =
                    __ldcg((const float4*)&d_hid1[(b2*Tt + t)*512 + kq*4]);
            }
            __syncthreads();
            mac_run(xr, wr1, 8, acc);
        }
        BAR_WAIT();             // bar2 wait (hidden behind rec MAC)
        if (t + 1 < Tt) {
            for (int i = tid; i < 4096; i += THR) {
                int b2 = i >> 6, e = i & 63;
                float v = 0.f;
                if (e < 3)       v = strks[(b2*Tt + t + 1)*3 + e];
                else if (e < 63) v = __ldcg(&d_wbuf[b2*60 + e - 3]);
                Xs[b2*XP + (e>>2)*SLC + 32 + (e&3)] = v;
            }
        }
        __syncthreads();
    }

    // ================= phase 2 =================
    {
        const float4* src = (const float4*)(d_P2 + bb*P2SZ);
        for (int i = tid; i < P2SZ/4; i += THR) ((float4*)W)[i] = src[i];
    }
    const float* wr2 = W + ks*P2KS + rq*4;
    __syncthreads();

    // preamble: acc(0) = MAC-A(h1(0)) + MAC-misc(0)   (h2(-1) = 0)
    ZERO_ACC(acc);
    for (int i = tid; i < 8192; i += THR) {
        int b2 = i >> 7, kq = i & 127;
        *(float4*)&Xs[b2*XP + (kq>>3)*SLC + (kq&7)*4] =
            __ldcg((const float4*)&d_hid1[(b2*Tt + 0)*512 + kq*4]);
    }
    __syncthreads();
    mac_run(xr, wr2, 8, acc);
    for (int i = tid; i < 4096; i += THR) {
        int b2 = i >> 6, e = i & 63;
        float v = 0.f;
        if (e < 3)       v = strks[(b2*Tt + 0)*3 + e];
        else if (e < 63) v = __ldcg(&d_win[(b2*Tt + 0)*60 + (e-3)]);
        Xs[b2*XP + (e>>2)*SLC + 32 + (e&3)] = v;
    }
    __syncthreads();
    mac_run(xr + 32, wr2 + 32*16, 1, acc);

    for (int t = 0; t < Tt; t++) {
        // acc holds full gates for step t
        KS_REDUCE(acc);
        if (lane < 4) {
            #pragma unroll
            for (int j = 0; j < 8; j++)
                *(float4*)&Gm[kh*1280 + (b0+j)*20 + rq*4] =
                    make_float4(acc[j][0], acc[j][1], acc[j][2], acc[j][3]);
        }
        __syncthreads();
        if (tid < 256) {
            int b2 = tid >> 2, uu = tid & 3;
            int u = bb*4 + uu;
            float ig = Gm[b2*20 +  0 + uu] + Gm[1280 + b2*20 +  0 + uu] + bi2[0];
            float fg = Gm[b2*20 +  4 + uu] + Gm[1280 + b2*20 +  4 + uu] + bi2[1];
            float gg = Gm[b2*20 +  8 + uu] + Gm[1280 + b2*20 +  8 + uu] + bi2[2];
            float og = Gm[b2*20 + 12 + uu] + Gm[1280 + b2*20 + 12 + uu] + bi2[3];
            float c = sigf(fg)*d_c2[b2*512 + u] + sigf(ig)*tanhf(gg);
            float h = sigf(og)*tanhf(c);
            d_c2[b2*512 + u] = c;
            d_hid2[(b2*Tt + t)*512 + u] = h;
        }
        if (t + 1 >= Tt) break;   // h2(799) written; done

        BAR_ARRIVE();             // bar: h2(t) ready

        // build step t+1: fill A = h1(t+1), MAC-A, fill misc(t+1) (overlaps wait)
        ZERO_ACC(acc);
        for (int i = tid; i < 8192; i += THR) {
            int b2 = i >> 7, kq = i & 127;
            *(float4*)&Xs[b2*XP + (kq>>3)*SLC + (kq&7)*4] =
                __ldcg((const float4*)&d_hid1[(b2*Tt + t + 1)*512 + kq*4]);
        }
        __syncthreads();
        mac_run(xr, wr2, 8, acc);
        for (int i = tid; i < 4096; i += THR) {
            int b2 = i >> 6, e = i & 63;
            float v = 0.f;
            if (e < 3)       v = strks[(b2*Tt + t + 1)*3 + e];
            else if (e < 63) v = __ldcg(&d_win[(b2*Tt + t + 1)*60 + (e-3)]);
            Xs[b2*XP + (e>>2)*SLC + 32 + (e&3)] = v;
        }
        BAR_WAIT();               // hidden behind fill-A + MAC-A
        mac_run(xr + 32, wr2 + 32*16, 1, acc);    // misc chunk
        // fill h2(t) into j0..31 (A consumed; WAIT's syncthreads ordered all MAC-A)
        for (int i = tid; i < 8192; i += THR) {
            int b2 = i >> 7, kq = i & 127;
            *(float4*)&Xs[b2*XP + (kq>>3)*SLC + (kq&7)*4] =
                __ldcg((const float4*)&d_hid2[(b2*Tt + t)*512 + kq*4]);
        }
        __syncthreads();
        mac_run(xr, wr2 + 36*16, 8, acc);         // h2 chunks
    }
}

// ---------------- MDN head ----------------
__global__ void mdn_kernel(const float* __restrict__ bmdn, float* __restrict__ out)
{
    __shared__ float rows[8*1024];
    __shared__ float pbuf[8*128];
    const int tid  = threadIdx.x;
    const int row0 = blockIdx.x*8;

    for (int idx = tid; idx < 8*1024; idx += 256) {
        int rr = idx >> 10, k2 = idx & 1023;
        int bt = row0 + rr;
        rows[idx] = (k2 < 512) ? d_hid1[bt*512 + k2] : d_hid2[bt*512 + (k2-512)];
    }
    __syncthreads();

    const int o    = tid & 127;
    const int half = tid >> 7;
    if (o < MDNO) {
        float acc[4];
        float bbv = bmdn[o];
        #pragma unroll
        for (int i = 0; i < 4; i++) acc[i] = bbv;
        const float* wr = &d_Weff[o*1024];
        for (int k2 = 0; k2 < 1024; k2 += 4) {
            float4 w = *(const float4*)(wr + k2);
            #pragma unroll
            for (int i = 0; i < 4; i++) {
                const float* x = &rows[(half*4 + i)*1024 + k2];
                acc[i] += w.x*x[0] + w.y*x[1] + w.z*x[2] + w.w*x[3];
            }
        }
        #pragma unroll
        for (int i = 0; i < 4; i++) pbuf[(half*4 + i)*128 + o] = acc[i];
    }
    __syncthreads();

    const int warp = tid >> 5, lane = tid & 31;
    const int bt = row0 + warp;
    const float* p = &pbuf[warp*128];

    float v = (lane < 20) ? p[lane] : -1e30f;
    float mx = v;
    #pragma unroll
    for (int off = 16; off; off >>= 1) mx = fmaxf(mx, __shfl_xor_sync(0xffffffffu, mx, off));
    float e = (lane < 20) ? expf(v - mx) : 0.f;
    float sum = e;
    #pragma unroll
    for (int off = 16; off; off >>= 1) sum += __shfl_xor_sync(0xffffffffu, sum, off);

    if (lane < 20) {
        float* base = out + BT;
        base[            bt*20 + lane] = e / sum;
        base[1*BT*20  +  bt*20 + lane] = p[20 + lane];
        base[2*BT*20  +  bt*20 + lane] = p[40 + lane];
        base[3*BT*20  +  bt*20 + lane] = expf(p[60 + lane]);
        base[4*BT*20  +  bt*20 + lane] = expf(p[80 + lane]);
        base[5*BT*20  +  bt*20 + lane] = tanhf(p[100 + lane]);
    }
    if (lane == 20) out[bt] = 1.f/(1.f + expf(-p[120]));
}

// ---------------- launch ----------------
extern "C" void kernel_launch(void* const* d_in, const int* in_sizes, int n_in,
                              void* d_out, int out_size)
{
    const float* strks   = (const float*)d_in[0];
    const float* sents_m = (const float*)d_in[3];
    const float* onehots = (const float*)d_in[4];
    const float* w_prev  = (const float*)d_in[5];
    const float* Wih1    = (const float*)d_in[6];
    const float* Whh1    = (const float*)d_in[7];
    const float* bih1    = (const float*)d_in[8];
    const float* bhh1    = (const float*)d_in[9];
    const float* Wih2    = (const float*)d_in[10];
    const float* Whh2    = (const float*)d_in[11];
    const float* bih2    = (const float*)d_in[12];
    const float* bhh2    = (const float*)d_in[13];
    const float* Wsw     = (const float*)d_in[14];
    const float* bsw     = (const float*)d_in[15];
    const float* Wmdn    = (const float*)d_in[16];
    const float* bmdn    = (const float*)d_in[17];
    float* out = (float*)d_out;

    cudaFuncSetAttribute(main_scan, cudaFuncAttributeMaxDynamicSharedMemorySize,
                         SM_TOT*sizeof(float));

    prep_pack1<<<(NBLK*P1SZ + 255)/256, 256>>>(Wih1, Whh1);
    prep_pack2<<<(NBLK*P2SZ + 255)/256, 256>>>(Wih2, Whh2);
    prep_misc <<<(MDNO*1024 + 255)/256, 256>>>(bih1, bhh1, bih2, bhh2, Wmdn, w_prev);

    main_scan<<<NBLK, THR, SM_TOT*sizeof(float)>>>(strks, sents_m, onehots, Wsw, bsw);
    mdn_kernel<<<BT/8, 256>>>(bmdn, out);
}